// round 1
// baseline (speedup 1.0000x reference)
#include <cuda_runtime.h>
#include <math.h>

#define B_    2
#define S_    4096
#define D_    2048
#define H_    16
#define DK_   128
#define DV_   128
#define SEG_  512
#define NSEG_ 8
#define DH_   8192
#define M_    (B_*S_)   // 8192 rows

// ---------------- scratch (device globals; no allocation allowed) ----------------
__device__ __align__(16) float g_q  [M_ * H_ * DK_];     // 64 MB
__device__ __align__(16) float g_k  [M_ * H_ * DK_];
__device__ __align__(16) float g_v  [M_ * H_ * DV_];
__device__ __align__(16) float g_att[M_ * H_ * DV_];
__device__ __align__(16) float g_ao [M_ * D_];
__device__ __align__(16) float g_hh [(size_t)M_ * DH_];  // 256 MB
__device__ __align__(16) float g_y  [M_ * D_];
__device__ __align__(16) float g_U  [B_*H_*NSEG_ * DK_ * DV_];
__device__ __align__(16) float g_zU [B_*H_*NSEG_ * DK_];
__device__ __align__(16) float g_mem[B_*H_*NSEG_ * DK_ * DV_];
__device__ __align__(16) float g_z  [B_*H_*NSEG_ * DK_];

__device__ __forceinline__ float elu1(float x) {          // elu(x)+1
    return x > 0.f ? x + 1.f : __expf(x);
}

// ---------------- generic SGEMM: C = A(MxK) * B(KxN) [+bias][+resid][relu] ------
__global__ void __launch_bounds__(256)
sgemm_kernel(const float* __restrict__ A, const float* __restrict__ Bm,
             float* __restrict__ C, int Mm, int Nn, int Kk,
             const float* __restrict__ bias, int relu,
             const float* __restrict__ resid)
{
    __shared__ float As[8 * 132];   // As[kk][row], padded
    __shared__ float Bs[8 * 132];   // Bs[kk][col], padded
    int tid  = threadIdx.x;
    int arow = tid >> 1, acol = (tid & 1) << 2;     // A: 128 rows x 8 k
    int brow = tid >> 5, bcol = (tid & 31) << 2;    // B: 8 k x 128 cols
    int tx = tid & 15, ty = tid >> 4;

    const float* Ag = A  + (size_t)blockIdx.y * 128 * Kk;
    const float* Bg = Bm + (size_t)blockIdx.x * 128;

    float acc[8][8];
#pragma unroll
    for (int i = 0; i < 8; i++)
#pragma unroll
        for (int j = 0; j < 8; j++) acc[i][j] = 0.f;

    for (int k0 = 0; k0 < Kk; k0 += 8) {
        float4 av = *(const float4*)(Ag + (size_t)arow * Kk + k0 + acol);
        As[(acol+0)*132 + arow] = av.x;
        As[(acol+1)*132 + arow] = av.y;
        As[(acol+2)*132 + arow] = av.z;
        As[(acol+3)*132 + arow] = av.w;
        *(float4*)(Bs + brow*132 + bcol) =
            *(const float4*)(Bg + (size_t)(k0 + brow) * Nn + bcol);
        __syncthreads();
#pragma unroll
        for (int kk = 0; kk < 8; kk++) {
            float a[8], b[8];
            *(float4*)(a)     = *(const float4*)(As + kk*132 + ty*8);
            *(float4*)(a + 4) = *(const float4*)(As + kk*132 + ty*8 + 4);
            *(float4*)(b)     = *(const float4*)(Bs + kk*132 + tx*8);
            *(float4*)(b + 4) = *(const float4*)(Bs + kk*132 + tx*8 + 4);
#pragma unroll
            for (int i = 0; i < 8; i++)
#pragma unroll
                for (int j = 0; j < 8; j++) acc[i][j] += a[i] * b[j];
        }
        __syncthreads();
    }

#pragma unroll
    for (int i = 0; i < 8; i++) {
        size_t row   = (size_t)blockIdx.y * 128 + ty*8 + i;
        size_t cbase = row * Nn + blockIdx.x * 128 + tx*8;
#pragma unroll
        for (int j4 = 0; j4 < 8; j4 += 4) {
            float4 o;
            o.x = acc[i][j4+0]; o.y = acc[i][j4+1];
            o.z = acc[i][j4+2]; o.w = acc[i][j4+3];
            int col = blockIdx.x * 128 + tx*8 + j4;
            if (bias) {
                float4 bb = *(const float4*)(bias + col);
                o.x += bb.x; o.y += bb.y; o.z += bb.z; o.w += bb.w;
            }
            if (resid) {
                float4 r = *(const float4*)(resid + cbase + j4);
                o.x += r.x; o.y += r.y; o.z += r.z; o.w += r.w;
            }
            if (relu) {
                o.x = fmaxf(o.x, 0.f); o.y = fmaxf(o.y, 0.f);
                o.z = fmaxf(o.z, 0.f); o.w = fmaxf(o.w, 0.f);
            }
            *(float4*)(C + cbase + j4) = o;
        }
    }
}

// ---------------- segment-local causal SDP attention (flash style) --------------
// grid (qt=8, seg=8, bh=32), 256 thr. 64 q-rows per block. Writes att_dot.
#define ATTN_SMEM_BYTES ((64*132 + 64*132 + 64*68 + 192) * 4)
__global__ void __launch_bounds__(256)
attn_dot_kernel(const float* __restrict__ q, const float* __restrict__ k,
                const float* __restrict__ v, float* __restrict__ att)
{
    extern __shared__ float sm[];
    float* Qs  = sm;                 // [64][132] row-major q tile
    float* KV  = Qs + 64*132;        // [64][132] K tile, then V tile
    float* Ps  = KV + 64*132;        // [64][68]  P[kcol][qrow]
    float* m_s = Ps + 64*68;         // [64]
    float* l_s = m_s + 64;           // [64]
    float* rs  = l_s + 64;           // [64]

    int qt = blockIdx.x, seg = blockIdx.y, bh = blockIdx.z;
    int b = bh >> 4, h = bh & 15;
    int tid = threadIdx.x, tx = tid & 15, ty = tid >> 4;
    const float scale = 0.08838834764831845f;   // 1/sqrt(128)
    const size_t rstride = (size_t)H_ * DK_;    // 2048
    size_t base = ((size_t)(b*S_ + seg*SEG_) * H_ + h) * DK_;

    for (int i = tid; i < 64*32; i += 256) {
        int r = i >> 5, c4 = (i & 31) << 2;
        *(float4*)(Qs + r*132 + c4) =
            *(const float4*)(q + base + (size_t)(qt*64 + r)*rstride + c4);
    }
    if (tid < 64) { m_s[tid] = -1e30f; l_s[tid] = 0.f; }

    float acc[4][8];
#pragma unroll
    for (int i = 0; i < 4; i++)
#pragma unroll
        for (int j = 0; j < 8; j++) acc[i][j] = 0.f;
    __syncthreads();

    for (int kt = 0; kt <= qt; kt++) {
        // load K tile
        for (int i = tid; i < 64*32; i += 256) {
            int r = i >> 5, c4 = (i & 31) << 2;
            *(float4*)(KV + r*132 + c4) =
                *(const float4*)(k + base + (size_t)(kt*64 + r)*rstride + c4);
        }
        __syncthreads();

        float s4[4][4];
#pragma unroll
        for (int i = 0; i < 4; i++)
#pragma unroll
            for (int j = 0; j < 4; j++) s4[i][j] = 0.f;

        for (int d = 0; d < 128; d += 4) {
            float4 qv[4], kv[4];
#pragma unroll
            for (int i = 0; i < 4; i++)
                qv[i] = *(const float4*)(Qs + (ty*4 + i)*132 + d);
#pragma unroll
            for (int j = 0; j < 4; j++)
                kv[j] = *(const float4*)(KV + (tx*4 + j)*132 + d);
#pragma unroll
            for (int i = 0; i < 4; i++)
#pragma unroll
                for (int j = 0; j < 4; j++)
                    s4[i][j] += qv[i].x*kv[j].x + qv[i].y*kv[j].y
                              + qv[i].z*kv[j].z + qv[i].w*kv[j].w;
        }

        // streaming softmax per q-row (row owned by 16 lanes, same ty)
#pragma unroll
        for (int i = 0; i < 4; i++) {
            int qr = ty*4 + i;
            float mx = -1e30f;
#pragma unroll
            for (int j = 0; j < 4; j++) {
                float sv = s4[i][j] * scale;
                if (kt == qt && (tx*4 + j) > qr) sv = -1e30f;
                s4[i][j] = sv;
                mx = fmaxf(mx, sv);
            }
#pragma unroll
            for (int o = 8; o >= 1; o >>= 1)
                mx = fmaxf(mx, __shfl_xor_sync(0xffffffffu, mx, o));
            float mold = m_s[qr];
            float mnew = fmaxf(mold, mx);
            float sum = 0.f;
#pragma unroll
            for (int j = 0; j < 4; j++) {
                float p = __expf(s4[i][j] - mnew);
                Ps[(tx*4 + j)*68 + qr] = p;
                sum += p;
            }
#pragma unroll
            for (int o = 8; o >= 1; o >>= 1)
                sum += __shfl_xor_sync(0xffffffffu, sum, o);
            if (tx == 0) {
                float rr = __expf(mold - mnew);
                rs[qr]  = rr;
                l_s[qr] = l_s[qr] * rr + sum;
                m_s[qr] = mnew;
            }
        }
        __syncthreads();                 // P visible, K reads finished

        // load V tile into KV
        for (int i = tid; i < 64*32; i += 256) {
            int r = i >> 5, c4 = (i & 31) << 2;
            *(float4*)(KV + r*132 + c4) =
                *(const float4*)(v + base + (size_t)(kt*64 + r)*rstride + c4);
        }
        __syncthreads();

        float rf[4];
#pragma unroll
        for (int i = 0; i < 4; i++) rf[i] = rs[ty*4 + i];
#pragma unroll
        for (int i = 0; i < 4; i++)
#pragma unroll
            for (int j = 0; j < 8; j++) acc[i][j] *= rf[i];

        for (int kk = 0; kk < 64; kk++) {
            float pv[4];
            *(float4*)pv = *(const float4*)(Ps + kk*68 + ty*4);
            float4 v0 = *(const float4*)(KV + kk*132 + tx*8);
            float4 v1 = *(const float4*)(KV + kk*132 + tx*8 + 4);
#pragma unroll
            for (int i = 0; i < 4; i++) {
                acc[i][0] += pv[i]*v0.x; acc[i][1] += pv[i]*v0.y;
                acc[i][2] += pv[i]*v0.z; acc[i][3] += pv[i]*v0.w;
                acc[i][4] += pv[i]*v1.x; acc[i][5] += pv[i]*v1.y;
                acc[i][6] += pv[i]*v1.z; acc[i][7] += pv[i]*v1.w;
            }
        }
        __syncthreads();                 // before KV/Ps reuse
    }

#pragma unroll
    for (int i = 0; i < 4; i++) {
        int qr = ty*4 + i;
        float inv = 1.f / l_s[qr];
        size_t o = base + (size_t)(qt*64 + qr)*rstride + tx*8;
        float4 o0, o1;
        o0.x = acc[i][0]*inv; o0.y = acc[i][1]*inv;
        o0.z = acc[i][2]*inv; o0.w = acc[i][3]*inv;
        o1.x = acc[i][4]*inv; o1.y = acc[i][5]*inv;
        o1.z = acc[i][6]*inv; o1.w = acc[i][7]*inv;
        *(float4*)(att + o)     = o0;
        *(float4*)(att + o + 4) = o1;
    }
}

// ---------------- per-segment memory update U = sig(K)^T V, zU = sum sig(K) -----
// grid 256 (= bh*8+seg), 256 thr
__global__ void __launch_bounds__(256)
memupd_kernel(const float* __restrict__ k, const float* __restrict__ v,
              float* __restrict__ U, float* __restrict__ zU)
{
    __shared__ float Ks[32*132];
    __shared__ float Vs[32*132];
    int seg = blockIdx.x & 7, bh = blockIdx.x >> 3;
    int b = bh >> 4, h = bh & 15;
    int tid = threadIdx.x, tx = tid & 15, ty = tid >> 4;
    size_t base = ((size_t)(b*S_ + seg*SEG_) * H_ + h) * DK_;

    float acc[8][8];
#pragma unroll
    for (int i = 0; i < 8; i++)
#pragma unroll
        for (int j = 0; j < 8; j++) acc[i][j] = 0.f;
    float zacc = 0.f;

    for (int s0 = 0; s0 < SEG_; s0 += 32) {
        for (int i = tid; i < 32*32; i += 256) {
            int r = i >> 5, c4 = (i & 31) << 2;
            float4 kv = *(const float4*)(k + base + (size_t)(s0 + r)*2048 + c4);
            kv.x = elu1(kv.x); kv.y = elu1(kv.y);
            kv.z = elu1(kv.z); kv.w = elu1(kv.w);
            *(float4*)(Ks + r*132 + c4) = kv;
            *(float4*)(Vs + r*132 + c4) =
                *(const float4*)(v + base + (size_t)(s0 + r)*2048 + c4);
        }
        __syncthreads();
        if (tid < 128) {
#pragma unroll 4
            for (int ss = 0; ss < 32; ss++) zacc += Ks[ss*132 + tid];
        }
        for (int ss = 0; ss < 32; ss++) {
            float a[8], bb[8];
            *(float4*)(a)      = *(const float4*)(Ks + ss*132 + ty*8);
            *(float4*)(a + 4)  = *(const float4*)(Ks + ss*132 + ty*8 + 4);
            *(float4*)(bb)     = *(const float4*)(Vs + ss*132 + tx*8);
            *(float4*)(bb + 4) = *(const float4*)(Vs + ss*132 + tx*8 + 4);
#pragma unroll
            for (int i = 0; i < 8; i++)
#pragma unroll
                for (int j = 0; j < 8; j++) acc[i][j] += a[i] * bb[j];
        }
        __syncthreads();
    }

    size_t ob = (size_t)blockIdx.x * (DK_*DV_);
#pragma unroll
    for (int i = 0; i < 8; i++)
#pragma unroll
        for (int j4 = 0; j4 < 8; j4 += 4) {
            float4 o;
            o.x = acc[i][j4+0]; o.y = acc[i][j4+1];
            o.z = acc[i][j4+2]; o.w = acc[i][j4+3];
            *(float4*)(U + ob + (ty*8 + i)*128 + tx*8 + j4) = o;
        }
    if (tid < 128) zU[(size_t)blockIdx.x*128 + tid] = zacc;
}

// ---------------- exclusive prefix over segments (mem0=0, z0=1/DK) --------------
__global__ void __launch_bounds__(256)
prefix_kernel(const float* __restrict__ U, const float* __restrict__ zU,
              float* __restrict__ Mem, float* __restrict__ Z)
{
    int bh = blockIdx.x, tid = threadIdx.x;
    for (int idx = tid; idx < DK_*DV_; idx += 256) {
        float run = 0.f;
#pragma unroll
        for (int sg = 0; sg < NSEG_; sg++) {
            size_t o = ((size_t)(bh*NSEG_ + sg)) * (DK_*DV_) + idx;
            Mem[o] = run;
            run += U[o];
        }
    }
    if (tid < 128) {
        float run = 1.f / 128.f;
#pragma unroll
        for (int sg = 0; sg < NSEG_; sg++) {
            size_t o = (size_t)(bh*NSEG_ + sg) * 128 + tid;
            Z[o] = run;
            run += zU[o];
        }
    }
}

// ---------------- retrieval + gate combine --------------------------------------
// grid 256 (= bh*8+seg), 256 thr. att := gate*mem_att + (1-gate)*att_dot
#define B3_SMEM_BYTES ((16384 + 128 + 32*132 + 32) * 4)
__global__ void __launch_bounds__(256)
retrieve_kernel(const float* __restrict__ q, const float* __restrict__ Mem,
                const float* __restrict__ Z, const float* __restrict__ betas,
                float* __restrict__ att)
{
    extern __shared__ float sm[];
    float* memS = sm;                // [128][128]
    float* zS   = memS + 16384;      // [128]
    float* sq   = zS + 128;          // [32][132] elu(q)+1 tile
    float* den  = sq + 32*132;       // [32]

    int seg = blockIdx.x & 7, bh = blockIdx.x >> 3;
    int b = bh >> 4, h = bh & 15;
    int tid = threadIdx.x, tx = tid & 15, ty = tid >> 4;
    size_t base = ((size_t)(b*S_ + seg*SEG_) * H_ + h) * DK_;
    size_t mb = (size_t)blockIdx.x * 16384;

    for (int i = tid; i < 4096; i += 256)
        *(float4*)(memS + i*4) = *(const float4*)(Mem + mb + i*4);
    if (tid < 128) zS[tid] = Z[(size_t)blockIdx.x*128 + tid];

    float gate[8];
#pragma unroll
    for (int j = 0; j < 8; j++)
        gate[j] = 1.f / (1.f + __expf(-betas[h*128 + tx*8 + j]));
    __syncthreads();

    for (int r0 = 0; r0 < SEG_; r0 += 32) {
        for (int i = tid; i < 32*32; i += 256) {
            int r = i >> 5, c4 = (i & 31) << 2;
            float4 qv = *(const float4*)(q + base + (size_t)(r0 + r)*2048 + c4);
            qv.x = elu1(qv.x); qv.y = elu1(qv.y);
            qv.z = elu1(qv.z); qv.w = elu1(qv.w);
            *(float4*)(sq + r*132 + c4) = qv;
        }
        __syncthreads();
        if (tid < 32) {
            float dsum = 0.f;
#pragma unroll 4
            for (int d = 0; d < 128; d++) dsum += sq[tid*132 + d] * zS[d];
            den[tid] = dsum;
        }
        __syncthreads();

        float am[2][8];
#pragma unroll
        for (int i = 0; i < 2; i++)
#pragma unroll
            for (int j = 0; j < 8; j++) am[i][j] = 0.f;

        for (int d = 0; d < 128; d++) {
            float a0 = sq[(ty*2 + 0)*132 + d];
            float a1 = sq[(ty*2 + 1)*132 + d];
            float4 m0 = *(const float4*)(memS + d*128 + tx*8);
            float4 m1 = *(const float4*)(memS + d*128 + tx*8 + 4);
            am[0][0] += a0*m0.x; am[0][1] += a0*m0.y; am[0][2] += a0*m0.z; am[0][3] += a0*m0.w;
            am[0][4] += a0*m1.x; am[0][5] += a0*m1.y; am[0][6] += a0*m1.z; am[0][7] += a0*m1.w;
            am[1][0] += a1*m0.x; am[1][1] += a1*m0.y; am[1][2] += a1*m0.z; am[1][3] += a1*m0.w;
            am[1][4] += a1*m1.x; am[1][5] += a1*m1.y; am[1][6] += a1*m1.z; am[1][7] += a1*m1.w;
        }

#pragma unroll
        for (int i = 0; i < 2; i++) {
            int r = r0 + ty*2 + i;
            float inv = 1.f / den[ty*2 + i];
            size_t o = base + (size_t)r*2048 + tx*8;
            float4 d0 = *(const float4*)(att + o);
            float4 d1 = *(const float4*)(att + o + 4);
            float4 o0, o1;
            o0.x = gate[0]*(am[i][0]*inv) + (1.f - gate[0])*d0.x;
            o0.y = gate[1]*(am[i][1]*inv) + (1.f - gate[1])*d0.y;
            o0.z = gate[2]*(am[i][2]*inv) + (1.f - gate[2])*d0.z;
            o0.w = gate[3]*(am[i][3]*inv) + (1.f - gate[3])*d0.w;
            o1.x = gate[4]*(am[i][4]*inv) + (1.f - gate[4])*d1.x;
            o1.y = gate[5]*(am[i][5]*inv) + (1.f - gate[5])*d1.y;
            o1.z = gate[6]*(am[i][6]*inv) + (1.f - gate[6])*d1.z;
            o1.w = gate[7]*(am[i][7]*inv) + (1.f - gate[7])*d1.w;
            *(float4*)(att + o)     = o0;
            *(float4*)(att + o + 4) = o1;
        }
        __syncthreads();
    }
}

// ---------------- LayerNorm -----------------------------------------------------
__global__ void __launch_bounds__(256)
ln_kernel(const float* __restrict__ y, const float* __restrict__ gg,
          const float* __restrict__ bb, float* __restrict__ out)
{
    size_t row = blockIdx.x;
    const float* p = y + row * D_;
    int tid = threadIdx.x;
    float4 v0 = *(const float4*)(p + tid*8);
    float4 v1 = *(const float4*)(p + tid*8 + 4);
    float s  = v0.x+v0.y+v0.z+v0.w + v1.x+v1.y+v1.z+v1.w;
    float s2 = v0.x*v0.x+v0.y*v0.y+v0.z*v0.z+v0.w*v0.w
             + v1.x*v1.x+v1.y*v1.y+v1.z*v1.z+v1.w*v1.w;
#pragma unroll
    for (int o = 16; o >= 1; o >>= 1) {
        s  += __shfl_xor_sync(0xffffffffu, s, o);
        s2 += __shfl_xor_sync(0xffffffffu, s2, o);
    }
    __shared__ float red[16];
    __shared__ float stat[2];
    int warp = tid >> 5, lane = tid & 31;
    if (lane == 0) { red[warp] = s; red[warp + 8] = s2; }
    __syncthreads();
    if (tid == 0) {
        float S = 0.f, S2 = 0.f;
#pragma unroll
        for (int w = 0; w < 8; w++) { S += red[w]; S2 += red[w + 8]; }
        float mean = S / (float)D_;
        float var  = S2 / (float)D_ - mean*mean;
        stat[0] = mean;
        stat[1] = rsqrtf(var + 1e-5f);
    }
    __syncthreads();
    float mean = stat[0], inv = stat[1];
    float4 g0 = *(const float4*)(gg + tid*8), g1 = *(const float4*)(gg + tid*8 + 4);
    float4 b0 = *(const float4*)(bb + tid*8), b1 = *(const float4*)(bb + tid*8 + 4);
    float4 o0, o1;
    o0.x = (v0.x-mean)*inv*g0.x + b0.x; o0.y = (v0.y-mean)*inv*g0.y + b0.y;
    o0.z = (v0.z-mean)*inv*g0.z + b0.z; o0.w = (v0.w-mean)*inv*g0.w + b0.w;
    o1.x = (v1.x-mean)*inv*g1.x + b1.x; o1.y = (v1.y-mean)*inv*g1.y + b1.y;
    o1.z = (v1.z-mean)*inv*g1.z + b1.z; o1.w = (v1.w-mean)*inv*g1.w + b1.w;
    *(float4*)(out + row*D_ + tid*8)     = o0;
    *(float4*)(out + row*D_ + tid*8 + 4) = o1;
}

// ---------------- launch --------------------------------------------------------
extern "C" void kernel_launch(void* const* d_in, const int* in_sizes, int n_in,
                              void* d_out, int out_size)
{
    const float* x     = (const float*)d_in[0];
    const float* Wq    = (const float*)d_in[1];
    const float* Wk    = (const float*)d_in[2];
    const float* Wv    = (const float*)d_in[3];
    const float* Wo    = (const float*)d_in[4];
    const float* betas = (const float*)d_in[5];
    const float* W1    = (const float*)d_in[6];
    const float* b1    = (const float*)d_in[7];
    const float* W2    = (const float*)d_in[8];
    const float* b2    = (const float*)d_in[9];
    const float* ln_g  = (const float*)d_in[10];
    const float* ln_b  = (const float*)d_in[11];
    float* out = (float*)d_out;

    float *q_, *k_, *v_, *att_, *ao_, *h_, *y_, *U_, *zU_, *mem_, *z_;
    cudaGetSymbolAddress((void**)&q_,   g_q);
    cudaGetSymbolAddress((void**)&k_,   g_k);
    cudaGetSymbolAddress((void**)&v_,   g_v);
    cudaGetSymbolAddress((void**)&att_, g_att);
    cudaGetSymbolAddress((void**)&ao_,  g_ao);
    cudaGetSymbolAddress((void**)&h_,   g_hh);
    cudaGetSymbolAddress((void**)&y_,   g_y);
    cudaGetSymbolAddress((void**)&U_,   g_U);
    cudaGetSymbolAddress((void**)&zU_,  g_zU);
    cudaGetSymbolAddress((void**)&mem_, g_mem);
    cudaGetSymbolAddress((void**)&z_,   g_z);

    cudaFuncSetAttribute(attn_dot_kernel,
        cudaFuncAttributeMaxDynamicSharedMemorySize, ATTN_SMEM_BYTES);
    cudaFuncSetAttribute(retrieve_kernel,
        cudaFuncAttributeMaxDynamicSharedMemorySize, B3_SMEM_BYTES);

    dim3 gProj(D_/128, M_/128);          // (16, 64)
    dim3 gMlp1(DH_/128, M_/128);         // (64, 64)

    // QKV projections
    sgemm_kernel<<<gProj, 256>>>(x, Wq, q_, M_, D_, D_, nullptr, 0, nullptr);
    sgemm_kernel<<<gProj, 256>>>(x, Wk, k_, M_, D_, D_, nullptr, 0, nullptr);
    sgemm_kernel<<<gProj, 256>>>(x, Wv, v_, M_, D_, D_, nullptr, 0, nullptr);

    // segment-local SDP attention (writes att_dot into g_att)
    attn_dot_kernel<<<dim3(8, 8, 32), 256, ATTN_SMEM_BYTES>>>(q_, k_, v_, att_);

    // Infini linear-memory path
    memupd_kernel<<<256, 256>>>(k_, v_, U_, zU_);
    prefix_kernel<<<32, 256>>>(U_, zU_, mem_, z_);
    retrieve_kernel<<<256, 256, B3_SMEM_BYTES>>>(q_, mem_, z_, betas, att_);

    // output projection + MLP (+residual) + LN
    sgemm_kernel<<<gProj, 256>>>(att_, Wo, ao_, M_, D_, D_, nullptr, 0, nullptr);
    sgemm_kernel<<<gMlp1, 256>>>(ao_, W1, h_, M_, DH_, D_, b1, 1, nullptr);
    sgemm_kernel<<<gProj, 256>>>(h_, W2, y_, M_, D_, DH_, b2, 0, x);
    ln_kernel<<<M_, 256>>>(y_, ln_g, ln_b, out);
}

// round 2
// speedup vs baseline: 2.7603x; 2.7603x over previous
#include <cuda_runtime.h>
#include <cuda_bf16.h>
#include <math.h>
#include <stdint.h>

#define B_    2
#define S_    4096
#define D_    2048
#define H_    16
#define DK_   128
#define DV_   128
#define SEG_  512
#define NSEG_ 8
#define DH_   8192
#define M_    (B_*S_)   // 8192 rows

// ---------------- scratch (device globals; no allocation allowed) ----------------
// fp32
__device__ __align__(16) float g_q  [M_ * H_ * DK_];
__device__ __align__(16) float g_k  [M_ * H_ * DK_];
__device__ __align__(16) float g_v  [M_ * H_ * DV_];
__device__ __align__(16) float g_att[M_ * H_ * DV_];
__device__ __align__(16) float g_y  [M_ * D_];
__device__ __align__(16) float g_U  [B_*H_*NSEG_ * DK_ * DV_];
__device__ __align__(16) float g_zU [B_*H_*NSEG_ * DK_];
__device__ __align__(16) float g_mem[B_*H_*NSEG_ * DK_ * DV_];
__device__ __align__(16) float g_z  [B_*H_*NSEG_ * DK_];
// bf16 hi/lo pairs
__device__ __align__(16) __nv_bfloat16 g_xh [M_ * D_],    g_xl [M_ * D_];
__device__ __align__(16) __nv_bfloat16 g_wqh[D_ * D_],    g_wql[D_ * D_];
__device__ __align__(16) __nv_bfloat16 g_wkh[D_ * D_],    g_wkl[D_ * D_];
__device__ __align__(16) __nv_bfloat16 g_wvh[D_ * D_],    g_wvl[D_ * D_];
__device__ __align__(16) __nv_bfloat16 g_woh[D_ * D_],    g_wol[D_ * D_];
__device__ __align__(16) __nv_bfloat16 g_w1h[D_ * DH_],   g_w1l[D_ * DH_];
__device__ __align__(16) __nv_bfloat16 g_w2h[DH_ * D_],   g_w2l[DH_ * D_];
__device__ __align__(16) __nv_bfloat16 g_ath[M_ * D_],    g_atl[M_ * D_];
__device__ __align__(16) __nv_bfloat16 g_aoh[M_ * D_],    g_aol[M_ * D_];
__device__ __align__(16) __nv_bfloat16 g_hhh[(size_t)M_ * DH_], g_hhl[(size_t)M_ * DH_];

__device__ __forceinline__ float elu1(float x) { return x > 0.f ? x + 1.f : __expf(x); }

// ================= bf16x3 tensor-core GEMM ======================================
// C(MxN fp32) = (Ahi+Alo)(MxK) * (Bhi+Blo)(KxN) dropping lo*lo.
// Block 128x128, BK=32, 8 warps, warp tile 32x64, mma.sync m16n8k16 bf16.

__device__ __forceinline__ void cp16(void* dst, const void* src) {
    uint32_t d = (uint32_t)__cvta_generic_to_shared(dst);
    asm volatile("cp.async.cg.shared.global [%0], [%1], 16;" :: "r"(d), "l"(src));
}

#define LDSM4(f, p) do { \
    uint32_t a_ = (uint32_t)__cvta_generic_to_shared(p); \
    asm volatile("ldmatrix.sync.aligned.m8n8.x4.shared.b16 {%0,%1,%2,%3}, [%4];" \
        : "=r"(f[0]), "=r"(f[1]), "=r"(f[2]), "=r"(f[3]) : "r"(a_)); \
} while (0)

#define LDSM4T(f, p) do { \
    uint32_t a_ = (uint32_t)__cvta_generic_to_shared(p); \
    asm volatile("ldmatrix.sync.aligned.m8n8.x4.trans.shared.b16 {%0,%1,%2,%3}, [%4];" \
        : "=r"(f[0]), "=r"(f[1]), "=r"(f[2]), "=r"(f[3]) : "r"(a_)); \
} while (0)

#define MMA16816(d, a, b0, b1) \
    asm volatile("mma.sync.aligned.m16n8k16.row.col.f32.bf16.bf16.f32 " \
        "{%0,%1,%2,%3}, {%4,%5,%6,%7}, {%8,%9}, {%0,%1,%2,%3};" \
        : "+f"(d[0]), "+f"(d[1]), "+f"(d[2]), "+f"(d[3]) \
        : "r"(a[0]), "r"(a[1]), "r"(a[2]), "r"(a[3]), "r"(b0), "r"(b1))

#define SA_STRIDE 40     // 32 + 8 pad (bf16 elems)   -> conflict-free ldmatrix
#define SB_STRIDE 136    // 128 + 8 pad
#define SA_STAGE  (128*SA_STRIDE)   // 5120
#define SB_STAGE  (32*SB_STRIDE)    // 4352
#define BGEMM_SMEM ((2*SA_STAGE*2 + 2*SB_STAGE*2) * 2)  // bytes = 75776

__device__ __forceinline__ void bg_load_stage(
    const __nv_bfloat16* __restrict__ Ahg, const __nv_bfloat16* __restrict__ Alg,
    const __nv_bfloat16* __restrict__ Bhg, const __nv_bfloat16* __restrict__ Blg,
    __nv_bfloat16* sAh, __nv_bfloat16* sAl, __nv_bfloat16* sBh, __nv_bfloat16* sBl,
    int tid, size_t m0, size_t n0, int Kk, int Nn, int k0)
{
    int arow = tid >> 2, achunk = (tid & 3) << 3;
    int brow = tid >> 3, bchunk = (tid & 7) << 3;
#pragma unroll
    for (int it = 0; it < 2; it++) {
        int r = arow + it * 64;
        size_t go = (m0 + r) * (size_t)Kk + k0 + achunk;
        cp16(sAh + r * SA_STRIDE + achunk, Ahg + go);
        cp16(sAl + r * SA_STRIDE + achunk, Alg + go);
    }
#pragma unroll
    for (int it = 0; it < 2; it++) {
        int c = bchunk + it * 64;
        size_t go = (size_t)(k0 + brow) * Nn + n0 + c;
        cp16(sBh + brow * SB_STRIDE + c, Bhg + go);
        cp16(sBl + brow * SB_STRIDE + c, Blg + go);
    }
    asm volatile("cp.async.commit_group;");
}

__global__ void __launch_bounds__(256)
bgemm_kernel(const __nv_bfloat16* __restrict__ Ahg, const __nv_bfloat16* __restrict__ Alg,
             const __nv_bfloat16* __restrict__ Bhg, const __nv_bfloat16* __restrict__ Blg,
             int Kk, int Nn,
             const float* __restrict__ bias, int relu, const float* __restrict__ resid,
             float* __restrict__ C,
             __nv_bfloat16* __restrict__ Ch, __nv_bfloat16* __restrict__ Cl)
{
    extern __shared__ __nv_bfloat16 smem[];
    __nv_bfloat16* sAh = smem;
    __nv_bfloat16* sAl = smem + 2*SA_STAGE;
    __nv_bfloat16* sBh = smem + 4*SA_STAGE;
    __nv_bfloat16* sBl = smem + 4*SA_STAGE + 2*SB_STAGE;

    int tid = threadIdx.x;
    int warp = tid >> 5, lane = tid & 31;
    int wm = warp >> 1, wn = warp & 1;
    size_t m0 = (size_t)blockIdx.y * 128;
    size_t n0 = (size_t)blockIdx.x * 128;

    float acc[2][8][4];
#pragma unroll
    for (int i = 0; i < 2; i++)
#pragma unroll
        for (int j = 0; j < 8; j++)
#pragma unroll
            for (int t = 0; t < 4; t++) acc[i][j][t] = 0.f;

    int nk = Kk >> 5;
    bg_load_stage(Ahg, Alg, Bhg, Blg, sAh, sAl, sBh, sBl, tid, m0, n0, Kk, Nn, 0);

    for (int kt = 0; kt < nk; kt++) {
        int cur = kt & 1;
        if (kt + 1 < nk) {
            bg_load_stage(Ahg, Alg, Bhg, Blg,
                          sAh + ((kt+1)&1)*SA_STAGE, sAl + ((kt+1)&1)*SA_STAGE,
                          sBh + ((kt+1)&1)*SB_STAGE, sBl + ((kt+1)&1)*SB_STAGE,
                          tid, m0, n0, Kk, Nn, (kt+1)*32);
            asm volatile("cp.async.wait_group 1;");
        } else {
            asm volatile("cp.async.wait_group 0;");
        }
        __syncthreads();

        __nv_bfloat16* ah = sAh + cur*SA_STAGE;
        __nv_bfloat16* al = sAl + cur*SA_STAGE;
        __nv_bfloat16* bh = sBh + cur*SB_STAGE;
        __nv_bfloat16* bl = sBl + cur*SB_STAGE;

#pragma unroll
        for (int k16 = 0; k16 < 32; k16 += 16) {
            uint32_t afh[2][4], afl[2][4], bfh[4][4], bfl[4][4];
#pragma unroll
            for (int mi = 0; mi < 2; mi++) {
                const __nv_bfloat16* pa = ah + (size_t)(wm*32 + mi*16 + (lane & 15)) * SA_STRIDE
                                             + k16 + (lane >> 4) * 8;
                LDSM4(afh[mi], pa);
                const __nv_bfloat16* pl = al + (size_t)(wm*32 + mi*16 + (lane & 15)) * SA_STRIDE
                                             + k16 + (lane >> 4) * 8;
                LDSM4(afl[mi], pl);
            }
#pragma unroll
            for (int nb = 0; nb < 4; nb++) {
                const __nv_bfloat16* pb = bh + (size_t)(k16 + (lane & 15)) * SB_STRIDE
                                             + wn*64 + nb*16 + (lane >> 4) * 8;
                LDSM4T(bfh[nb], pb);
                const __nv_bfloat16* pq = bl + (size_t)(k16 + (lane & 15)) * SB_STRIDE
                                             + wn*64 + nb*16 + (lane >> 4) * 8;
                LDSM4T(bfl[nb], pq);
            }
#pragma unroll
            for (int mi = 0; mi < 2; mi++)
#pragma unroll
                for (int ni = 0; ni < 8; ni++) {
                    int nb = ni >> 1, sel = (ni & 1) * 2;
                    MMA16816(acc[mi][ni], afh[mi], bfh[nb][sel], bfh[nb][sel+1]);
                    MMA16816(acc[mi][ni], afh[mi], bfl[nb][sel], bfl[nb][sel+1]);
                    MMA16816(acc[mi][ni], afl[mi], bfh[nb][sel], bfh[nb][sel+1]);
                }
        }
        __syncthreads();
    }

    // epilogue
#pragma unroll
    for (int mi = 0; mi < 2; mi++)
#pragma unroll
        for (int ni = 0; ni < 8; ni++) {
            int col = wn*64 + ni*8 + (lane & 3) * 2;
#pragma unroll
            for (int hh = 0; hh < 2; hh++) {
                int row = wm*32 + mi*16 + (lane >> 2) + hh*8;
                float v0 = acc[mi][ni][hh*2], v1 = acc[mi][ni][hh*2+1];
                size_t o = (m0 + row) * (size_t)Nn + n0 + col;
                if (bias) { v0 += bias[n0+col]; v1 += bias[n0+col+1]; }
                if (resid) { v0 += resid[o]; v1 += resid[o+1]; }
                if (relu) { v0 = fmaxf(v0, 0.f); v1 = fmaxf(v1, 0.f); }
                if (C) { C[o] = v0; C[o+1] = v1; }
                if (Ch) {
                    __nv_bfloat16 h0 = __float2bfloat16(v0);
                    __nv_bfloat16 h1 = __float2bfloat16(v1);
                    __nv_bfloat162 hp; hp.x = h0; hp.y = h1;
                    *(__nv_bfloat162*)(Ch + o) = hp;
                    __nv_bfloat162 lp;
                    lp.x = __float2bfloat16(v0 - __bfloat162float(h0));
                    lp.y = __float2bfloat16(v1 - __bfloat162float(h1));
                    *(__nv_bfloat162*)(Cl + o) = lp;
                }
            }
        }
}

// ---------------- fp32 -> bf16 hi/lo split --------------------------------------
__global__ void __launch_bounds__(256)
split_kernel(const float4* __restrict__ in, __nv_bfloat162* __restrict__ hi,
             __nv_bfloat162* __restrict__ lo, int nquads)
{
    int i = blockIdx.x * 256 + threadIdx.x;
    if (i >= nquads) return;
    float4 v = in[i];
    __nv_bfloat16 hx = __float2bfloat16(v.x), hy = __float2bfloat16(v.y);
    __nv_bfloat16 hz = __float2bfloat16(v.z), hw = __float2bfloat16(v.w);
    __nv_bfloat162 h0; h0.x = hx; h0.y = hy;
    __nv_bfloat162 h1; h1.x = hz; h1.y = hw;
    hi[2*i] = h0; hi[2*i+1] = h1;
    __nv_bfloat162 l0, l1;
    l0.x = __float2bfloat16(v.x - __bfloat162float(hx));
    l0.y = __float2bfloat16(v.y - __bfloat162float(hy));
    l1.x = __float2bfloat16(v.z - __bfloat162float(hz));
    l1.y = __float2bfloat16(v.w - __bfloat162float(hw));
    lo[2*i] = l0; lo[2*i+1] = l1;
}

// ---------------- segment-local causal SDP attention (flash style) --------------
#define ATTN_SMEM_BYTES ((64*132 + 64*132 + 64*68 + 192) * 4)
__global__ void __launch_bounds__(256)
attn_dot_kernel(const float* __restrict__ q, const float* __restrict__ k,
                const float* __restrict__ v, float* __restrict__ att)
{
    extern __shared__ float sm[];
    float* Qs  = sm;
    float* KV  = Qs + 64*132;
    float* Ps  = KV + 64*132;
    float* m_s = Ps + 64*68;
    float* l_s = m_s + 64;
    float* rs  = l_s + 64;

    int qt = blockIdx.x, seg = blockIdx.y, bh = blockIdx.z;
    int b = bh >> 4, h = bh & 15;
    int tid = threadIdx.x, tx = tid & 15, ty = tid >> 4;
    const float scale = 0.08838834764831845f;
    const size_t rstride = (size_t)H_ * DK_;
    size_t base = ((size_t)(b*S_ + seg*SEG_) * H_ + h) * DK_;

    for (int i = tid; i < 64*32; i += 256) {
        int r = i >> 5, c4 = (i & 31) << 2;
        *(float4*)(Qs + r*132 + c4) =
            *(const float4*)(q + base + (size_t)(qt*64 + r)*rstride + c4);
    }
    if (tid < 64) { m_s[tid] = -1e30f; l_s[tid] = 0.f; }

    float acc[4][8];
#pragma unroll
    for (int i = 0; i < 4; i++)
#pragma unroll
        for (int j = 0; j < 8; j++) acc[i][j] = 0.f;
    __syncthreads();

    for (int kt = 0; kt <= qt; kt++) {
        for (int i = tid; i < 64*32; i += 256) {
            int r = i >> 5, c4 = (i & 31) << 2;
            *(float4*)(KV + r*132 + c4) =
                *(const float4*)(k + base + (size_t)(kt*64 + r)*rstride + c4);
        }
        __syncthreads();

        float s4[4][4];
#pragma unroll
        for (int i = 0; i < 4; i++)
#pragma unroll
            for (int j = 0; j < 4; j++) s4[i][j] = 0.f;

        for (int d = 0; d < 128; d += 4) {
            float4 qv[4], kv[4];
#pragma unroll
            for (int i = 0; i < 4; i++)
                qv[i] = *(const float4*)(Qs + (ty*4 + i)*132 + d);
#pragma unroll
            for (int j = 0; j < 4; j++)
                kv[j] = *(const float4*)(KV + (tx*4 + j)*132 + d);
#pragma unroll
            for (int i = 0; i < 4; i++)
#pragma unroll
                for (int j = 0; j < 4; j++)
                    s4[i][j] += qv[i].x*kv[j].x + qv[i].y*kv[j].y
                              + qv[i].z*kv[j].z + qv[i].w*kv[j].w;
        }

#pragma unroll
        for (int i = 0; i < 4; i++) {
            int qr = ty*4 + i;
            float mx = -1e30f;
#pragma unroll
            for (int j = 0; j < 4; j++) {
                float sv = s4[i][j] * scale;
                if (kt == qt && (tx*4 + j) > qr) sv = -1e30f;
                s4[i][j] = sv;
                mx = fmaxf(mx, sv);
            }
#pragma unroll
            for (int o = 8; o >= 1; o >>= 1)
                mx = fmaxf(mx, __shfl_xor_sync(0xffffffffu, mx, o));
            float mold = m_s[qr];
            float mnew = fmaxf(mold, mx);
            float sum = 0.f;
#pragma unroll
            for (int j = 0; j < 4; j++) {
                float p = __expf(s4[i][j] - mnew);
                Ps[(tx*4 + j)*68 + qr] = p;
                sum += p;
            }
#pragma unroll
            for (int o = 8; o >= 1; o >>= 1)
                sum += __shfl_xor_sync(0xffffffffu, sum, o);
            if (tx == 0) {
                float rr = __expf(mold - mnew);
                rs[qr]  = rr;
                l_s[qr] = l_s[qr] * rr + sum;
                m_s[qr] = mnew;
            }
        }
        __syncthreads();

        for (int i = tid; i < 64*32; i += 256) {
            int r = i >> 5, c4 = (i & 31) << 2;
            *(float4*)(KV + r*132 + c4) =
                *(const float4*)(v + base + (size_t)(kt*64 + r)*rstride + c4);
        }
        __syncthreads();

        float rf[4];
#pragma unroll
        for (int i = 0; i < 4; i++) rf[i] = rs[ty*4 + i];
#pragma unroll
        for (int i = 0; i < 4; i++)
#pragma unroll
            for (int j = 0; j < 8; j++) acc[i][j] *= rf[i];

        for (int kk = 0; kk < 64; kk++) {
            float pv[4];
            *(float4*)pv = *(const float4*)(Ps + kk*68 + ty*4);
            float4 v0 = *(const float4*)(KV + kk*132 + tx*8);
            float4 v1 = *(const float4*)(KV + kk*132 + tx*8 + 4);
#pragma unroll
            for (int i = 0; i < 4; i++) {
                acc[i][0] += pv[i]*v0.x; acc[i][1] += pv[i]*v0.y;
                acc[i][2] += pv[i]*v0.z; acc[i][3] += pv[i]*v0.w;
                acc[i][4] += pv[i]*v1.x; acc[i][5] += pv[i]*v1.y;
                acc[i][6] += pv[i]*v1.z; acc[i][7] += pv[i]*v1.w;
            }
        }
        __syncthreads();
    }

#pragma unroll
    for (int i = 0; i < 4; i++) {
        int qr = ty*4 + i;
        float inv = 1.f / l_s[qr];
        size_t o = base + (size_t)(qt*64 + qr)*rstride + tx*8;
        float4 o0, o1;
        o0.x = acc[i][0]*inv; o0.y = acc[i][1]*inv;
        o0.z = acc[i][2]*inv; o0.w = acc[i][3]*inv;
        o1.x = acc[i][4]*inv; o1.y = acc[i][5]*inv;
        o1.z = acc[i][6]*inv; o1.w = acc[i][7]*inv;
        *(float4*)(att + o)     = o0;
        *(float4*)(att + o + 4) = o1;
    }
}

// ---------------- per-segment memory update U = sig(K)^T V, zU = sum sig(K) -----
__global__ void __launch_bounds__(256)
memupd_kernel(const float* __restrict__ k, const float* __restrict__ v,
              float* __restrict__ U, float* __restrict__ zU)
{
    __shared__ float Ks[32*132];
    __shared__ float Vs[32*132];
    int seg = blockIdx.x & 7, bh = blockIdx.x >> 3;
    int b = bh >> 4, h = bh & 15;
    int tid = threadIdx.x, tx = tid & 15, ty = tid >> 4;
    size_t base = ((size_t)(b*S_ + seg*SEG_) * H_ + h) * DK_;

    float acc[8][8];
#pragma unroll
    for (int i = 0; i < 8; i++)
#pragma unroll
        for (int j = 0; j < 8; j++) acc[i][j] = 0.f;
    float zacc = 0.f;

    for (int s0 = 0; s0 < SEG_; s0 += 32) {
        for (int i = tid; i < 32*32; i += 256) {
            int r = i >> 5, c4 = (i & 31) << 2;
            float4 kv = *(const float4*)(k + base + (size_t)(s0 + r)*2048 + c4);
            kv.x = elu1(kv.x); kv.y = elu1(kv.y);
            kv.z = elu1(kv.z); kv.w = elu1(kv.w);
            *(float4*)(Ks + r*132 + c4) = kv;
            *(float4*)(Vs + r*132 + c4) =
                *(const float4*)(v + base + (size_t)(s0 + r)*2048 + c4);
        }
        __syncthreads();
        if (tid < 128) {
#pragma unroll 4
            for (int ss = 0; ss < 32; ss++) zacc += Ks[ss*132 + tid];
        }
        for (int ss = 0; ss < 32; ss++) {
            float a[8], bb[8];
            *(float4*)(a)      = *(const float4*)(Ks + ss*132 + ty*8);
            *(float4*)(a + 4)  = *(const float4*)(Ks + ss*132 + ty*8 + 4);
            *(float4*)(bb)     = *(const float4*)(Vs + ss*132 + tx*8);
            *(float4*)(bb + 4) = *(const float4*)(Vs + ss*132 + tx*8 + 4);
#pragma unroll
            for (int i = 0; i < 8; i++)
#pragma unroll
                for (int j = 0; j < 8; j++) acc[i][j] += a[i] * bb[j];
        }
        __syncthreads();
    }

    size_t ob = (size_t)blockIdx.x * (DK_*DV_);
#pragma unroll
    for (int i = 0; i < 8; i++)
#pragma unroll
        for (int j4 = 0; j4 < 8; j4 += 4) {
            float4 o;
            o.x = acc[i][j4+0]; o.y = acc[i][j4+1];
            o.z = acc[i][j4+2]; o.w = acc[i][j4+3];
            *(float4*)(U + ob + (ty*8 + i)*128 + tx*8 + j4) = o;
        }
    if (tid < 128) zU[(size_t)blockIdx.x*128 + tid] = zacc;
}

// ---------------- exclusive prefix over segments --------------------------------
__global__ void __launch_bounds__(256)
prefix_kernel(const float* __restrict__ U, const float* __restrict__ zU,
              float* __restrict__ Mem, float* __restrict__ Z)
{
    int bh = blockIdx.x, tid = threadIdx.x;
    for (int idx = tid; idx < DK_*DV_; idx += 256) {
        float run = 0.f;
#pragma unroll
        for (int sg = 0; sg < NSEG_; sg++) {
            size_t o = ((size_t)(bh*NSEG_ + sg)) * (DK_*DV_) + idx;
            Mem[o] = run;
            run += U[o];
        }
    }
    if (tid < 128) {
        float run = 1.f / 128.f;
#pragma unroll
        for (int sg = 0; sg < NSEG_; sg++) {
            size_t o = (size_t)(bh*NSEG_ + sg) * 128 + tid;
            Z[o] = run;
            run += zU[o];
        }
    }
}

// ---------------- retrieval + gate combine --------------------------------------
#define B3_SMEM_BYTES ((16384 + 128 + 32*132 + 32) * 4)
__global__ void __launch_bounds__(256)
retrieve_kernel(const float* __restrict__ q, const float* __restrict__ Mem,
                const float* __restrict__ Z, const float* __restrict__ betas,
                float* __restrict__ att)
{
    extern __shared__ float sm[];
    float* memS = sm;
    float* zS   = memS + 16384;
    float* sq   = zS + 128;
    float* den  = sq + 32*132;

    int seg = blockIdx.x & 7, bh = blockIdx.x >> 3;
    int b = bh >> 4, h = bh & 15;
    int tid = threadIdx.x, tx = tid & 15, ty = tid >> 4;
    size_t base = ((size_t)(b*S_ + seg*SEG_) * H_ + h) * DK_;
    size_t mb = (size_t)blockIdx.x * 16384;

    for (int i = tid; i < 4096; i += 256)
        *(float4*)(memS + i*4) = *(const float4*)(Mem + mb + i*4);
    if (tid < 128) zS[tid] = Z[(size_t)blockIdx.x*128 + tid];

    float gate[8];
#pragma unroll
    for (int j = 0; j < 8; j++)
        gate[j] = 1.f / (1.f + __expf(-betas[h*128 + tx*8 + j]));
    __syncthreads();

    for (int r0 = 0; r0 < SEG_; r0 += 32) {
        for (int i = tid; i < 32*32; i += 256) {
            int r = i >> 5, c4 = (i & 31) << 2;
            float4 qv = *(const float4*)(q + base + (size_t)(r0 + r)*2048 + c4);
            qv.x = elu1(qv.x); qv.y = elu1(qv.y);
            qv.z = elu1(qv.z); qv.w = elu1(qv.w);
            *(float4*)(sq + r*132 + c4) = qv;
        }
        __syncthreads();
        if (tid < 32) {
            float dsum = 0.f;
#pragma unroll 4
            for (int d = 0; d < 128; d++) dsum += sq[tid*132 + d] * zS[d];
            den[tid] = dsum;
        }
        __syncthreads();

        float am[2][8];
#pragma unroll
        for (int i = 0; i < 2; i++)
#pragma unroll
            for (int j = 0; j < 8; j++) am[i][j] = 0.f;

        for (int d = 0; d < 128; d++) {
            float a0 = sq[(ty*2 + 0)*132 + d];
            float a1 = sq[(ty*2 + 1)*132 + d];
            float4 m0 = *(const float4*)(memS + d*128 + tx*8);
            float4 m1 = *(const float4*)(memS + d*128 + tx*8 + 4);
            am[0][0] += a0*m0.x; am[0][1] += a0*m0.y; am[0][2] += a0*m0.z; am[0][3] += a0*m0.w;
            am[0][4] += a0*m1.x; am[0][5] += a0*m1.y; am[0][6] += a0*m1.z; am[0][7] += a0*m1.w;
            am[1][0] += a1*m0.x; am[1][1] += a1*m0.y; am[1][2] += a1*m0.z; am[1][3] += a1*m0.w;
            am[1][4] += a1*m1.x; am[1][5] += a1*m1.y; am[1][6] += a1*m1.z; am[1][7] += a1*m1.w;
        }

#pragma unroll
        for (int i = 0; i < 2; i++) {
            int r = r0 + ty*2 + i;
            float inv = 1.f / den[ty*2 + i];
            size_t o = base + (size_t)r*2048 + tx*8;
            float4 d0 = *(const float4*)(att + o);
            float4 d1 = *(const float4*)(att + o + 4);
            float4 o0, o1;
            o0.x = gate[0]*(am[i][0]*inv) + (1.f - gate[0])*d0.x;
            o0.y = gate[1]*(am[i][1]*inv) + (1.f - gate[1])*d0.y;
            o0.z = gate[2]*(am[i][2]*inv) + (1.f - gate[2])*d0.z;
            o0.w = gate[3]*(am[i][3]*inv) + (1.f - gate[3])*d0.w;
            o1.x = gate[4]*(am[i][4]*inv) + (1.f - gate[4])*d1.x;
            o1.y = gate[5]*(am[i][5]*inv) + (1.f - gate[5])*d1.y;
            o1.z = gate[6]*(am[i][6]*inv) + (1.f - gate[6])*d1.z;
            o1.w = gate[7]*(am[i][7]*inv) + (1.f - gate[7])*d1.w;
            *(float4*)(att + o)     = o0;
            *(float4*)(att + o + 4) = o1;
        }
        __syncthreads();
    }
}

// ---------------- LayerNorm -----------------------------------------------------
__global__ void __launch_bounds__(256)
ln_kernel(const float* __restrict__ y, const float* __restrict__ gg,
          const float* __restrict__ bb, float* __restrict__ out)
{
    size_t row = blockIdx.x;
    const float* p = y + row * D_;
    int tid = threadIdx.x;
    float4 v0 = *(const float4*)(p + tid*8);
    float4 v1 = *(const float4*)(p + tid*8 + 4);
    float s  = v0.x+v0.y+v0.z+v0.w + v1.x+v1.y+v1.z+v1.w;
    float s2 = v0.x*v0.x+v0.y*v0.y+v0.z*v0.z+v0.w*v0.w
             + v1.x*v1.x+v1.y*v1.y+v1.z*v1.z+v1.w*v1.w;
#pragma unroll
    for (int o = 16; o >= 1; o >>= 1) {
        s  += __shfl_xor_sync(0xffffffffu, s, o);
        s2 += __shfl_xor_sync(0xffffffffu, s2, o);
    }
    __shared__ float red[16];
    __shared__ float stat[2];
    int warp = tid >> 5, lane = tid & 31;
    if (lane == 0) { red[warp] = s; red[warp + 8] = s2; }
    __syncthreads();
    if (tid == 0) {
        float S = 0.f, S2 = 0.f;
#pragma unroll
        for (int w = 0; w < 8; w++) { S += red[w]; S2 += red[w + 8]; }
        float mean = S / (float)D_;
        float var  = S2 / (float)D_ - mean*mean;
        stat[0] = mean;
        stat[1] = rsqrtf(var + 1e-5f);
    }
    __syncthreads();
    float mean = stat[0], inv = stat[1];
    float4 g0 = *(const float4*)(gg + tid*8), g1 = *(const float4*)(gg + tid*8 + 4);
    float4 b0 = *(const float4*)(bb + tid*8), b1 = *(const float4*)(bb + tid*8 + 4);
    float4 o0, o1;
    o0.x = (v0.x-mean)*inv*g0.x + b0.x; o0.y = (v0.y-mean)*inv*g0.y + b0.y;
    o0.z = (v0.z-mean)*inv*g0.z + b0.z; o0.w = (v0.w-mean)*inv*g0.w + b0.w;
    o1.x = (v1.x-mean)*inv*g1.x + b1.x; o1.y = (v1.y-mean)*inv*g1.y + b1.y;
    o1.z = (v1.z-mean)*inv*g1.z + b1.z; o1.w = (v1.w-mean)*inv*g1.w + b1.w;
    *(float4*)(out + row*D_ + tid*8)     = o0;
    *(float4*)(out + row*D_ + tid*8 + 4) = o1;
}

// ---------------- launch --------------------------------------------------------
static inline void split_launch(const float* src, __nv_bfloat16* hi, __nv_bfloat16* lo,
                                size_t nelems)
{
    int nq = (int)(nelems / 4);
    split_kernel<<<(nq + 255)/256, 256>>>((const float4*)src,
                                          (__nv_bfloat162*)hi, (__nv_bfloat162*)lo, nq);
}

extern "C" void kernel_launch(void* const* d_in, const int* in_sizes, int n_in,
                              void* d_out, int out_size)
{
    const float* x     = (const float*)d_in[0];
    const float* Wq    = (const float*)d_in[1];
    const float* Wk    = (const float*)d_in[2];
    const float* Wv    = (const float*)d_in[3];
    const float* Wo    = (const float*)d_in[4];
    const float* betas = (const float*)d_in[5];
    const float* W1    = (const float*)d_in[6];
    const float* b1    = (const float*)d_in[7];
    const float* W2    = (const float*)d_in[8];
    const float* b2    = (const float*)d_in[9];
    const float* ln_g  = (const float*)d_in[10];
    const float* ln_b  = (const float*)d_in[11];
    float* out = (float*)d_out;

    float *q_, *k_, *v_, *att_, *y_, *U_, *zU_, *mem_, *z_;
    cudaGetSymbolAddress((void**)&q_,   g_q);
    cudaGetSymbolAddress((void**)&k_,   g_k);
    cudaGetSymbolAddress((void**)&v_,   g_v);
    cudaGetSymbolAddress((void**)&att_, g_att);
    cudaGetSymbolAddress((void**)&y_,   g_y);
    cudaGetSymbolAddress((void**)&U_,   g_U);
    cudaGetSymbolAddress((void**)&zU_,  g_zU);
    cudaGetSymbolAddress((void**)&mem_, g_mem);
    cudaGetSymbolAddress((void**)&z_,   g_z);

    __nv_bfloat16 *xh,*xl,*wqh,*wql,*wkh,*wkl,*wvh,*wvl,*woh,*wol,
                  *w1h,*w1l,*w2h,*w2l,*ath,*atl,*aoh,*aol,*hhh,*hhl;
    cudaGetSymbolAddress((void**)&xh,  g_xh);  cudaGetSymbolAddress((void**)&xl,  g_xl);
    cudaGetSymbolAddress((void**)&wqh, g_wqh); cudaGetSymbolAddress((void**)&wql, g_wql);
    cudaGetSymbolAddress((void**)&wkh, g_wkh); cudaGetSymbolAddress((void**)&wkl, g_wkl);
    cudaGetSymbolAddress((void**)&wvh, g_wvh); cudaGetSymbolAddress((void**)&wvl, g_wvl);
    cudaGetSymbolAddress((void**)&woh, g_woh); cudaGetSymbolAddress((void**)&wol, g_wol);
    cudaGetSymbolAddress((void**)&w1h, g_w1h); cudaGetSymbolAddress((void**)&w1l, g_w1l);
    cudaGetSymbolAddress((void**)&w2h, g_w2h); cudaGetSymbolAddress((void**)&w2l, g_w2l);
    cudaGetSymbolAddress((void**)&ath, g_ath); cudaGetSymbolAddress((void**)&atl, g_atl);
    cudaGetSymbolAddress((void**)&aoh, g_aoh); cudaGetSymbolAddress((void**)&aol, g_aol);
    cudaGetSymbolAddress((void**)&hhh, g_hhh); cudaGetSymbolAddress((void**)&hhl, g_hhl);

    cudaFuncSetAttribute(bgemm_kernel,
        cudaFuncAttributeMaxDynamicSharedMemorySize, BGEMM_SMEM);
    cudaFuncSetAttribute(attn_dot_kernel,
        cudaFuncAttributeMaxDynamicSharedMemorySize, ATTN_SMEM_BYTES);
    cudaFuncSetAttribute(retrieve_kernel,
        cudaFuncAttributeMaxDynamicSharedMemorySize, B3_SMEM_BYTES);

    // splits (weights + x)
    split_launch(x,  xh,  xl,  (size_t)M_ * D_);
    split_launch(Wq, wqh, wql, (size_t)D_ * D_);
    split_launch(Wk, wkh, wkl, (size_t)D_ * D_);
    split_launch(Wv, wvh, wvl, (size_t)D_ * D_);
    split_launch(Wo, woh, wol, (size_t)D_ * D_);
    split_launch(W1, w1h, w1l, (size_t)D_ * DH_);
    split_launch(W2, w2h, w2l, (size_t)DH_ * D_);

    dim3 gProj(D_/128, M_/128);          // (16, 64)
    dim3 gMlp1(DH_/128, M_/128);         // (64, 64)

    // QKV projections (tensor cores, fp32 out)
    bgemm_kernel<<<gProj, 256, BGEMM_SMEM>>>(xh, xl, wqh, wql, D_, D_,
        nullptr, 0, nullptr, q_, nullptr, nullptr);
    bgemm_kernel<<<gProj, 256, BGEMM_SMEM>>>(xh, xl, wkh, wkl, D_, D_,
        nullptr, 0, nullptr, k_, nullptr, nullptr);
    bgemm_kernel<<<gProj, 256, BGEMM_SMEM>>>(xh, xl, wvh, wvl, D_, D_,
        nullptr, 0, nullptr, v_, nullptr, nullptr);

    // attention paths (fp32)
    attn_dot_kernel<<<dim3(8, 8, 32), 256, ATTN_SMEM_BYTES>>>(q_, k_, v_, att_);
    memupd_kernel<<<256, 256>>>(k_, v_, U_, zU_);
    prefix_kernel<<<32, 256>>>(U_, zU_, mem_, z_);
    retrieve_kernel<<<256, 256, B3_SMEM_BYTES>>>(q_, mem_, z_, betas, att_);

    // att -> bf16, then Wo / MLP chain on tensor cores
    split_launch(att_, ath, atl, (size_t)M_ * D_);
    bgemm_kernel<<<gProj, 256, BGEMM_SMEM>>>(ath, atl, woh, wol, D_, D_,
        nullptr, 0, nullptr, nullptr, aoh, aol);
    bgemm_kernel<<<gMlp1, 256, BGEMM_SMEM>>>(aoh, aol, w1h, w1l, D_, DH_,
        b1, 1, nullptr, nullptr, hhh, hhl);
    bgemm_kernel<<<gProj, 256, BGEMM_SMEM>>>(hhh, hhl, w2h, w2l, DH_, D_,
        b2, 0, x, y_, nullptr, nullptr);
    ln_kernel<<<M_, 256>>>(y_, ln_g, ln_b, out);
}

// round 3
// speedup vs baseline: 3.2126x; 1.1639x over previous
#include <cuda_runtime.h>
#include <cuda_bf16.h>
#include <math.h>
#include <stdint.h>

#define B_    2
#define S_    4096
#define D_    2048
#define H_    16
#define DK_   128
#define DV_   128
#define SEG_  512
#define NSEG_ 8
#define DH_   8192
#define M_    (B_*S_)   // 8192 rows

// ---------------- scratch (device globals; no allocation allowed) ----------------
__device__ __align__(16) float g_att[M_ * H_ * DV_];
__device__ __align__(16) float g_y  [M_ * D_];
__device__ __align__(16) float g_U  [B_*H_*NSEG_ * DK_ * DV_];
__device__ __align__(16) float g_zU [B_*H_*NSEG_ * DK_];
__device__ __align__(16) float g_mem[B_*H_*NSEG_ * DK_ * DV_];
__device__ __align__(16) float g_z  [B_*H_*NSEG_ * DK_];
// bf16 hi/lo pairs
__device__ __align__(16) __nv_bfloat16 g_xh [M_ * D_],    g_xl [M_ * D_];
__device__ __align__(16) __nv_bfloat16 g_wqh[D_ * D_],    g_wql[D_ * D_];
__device__ __align__(16) __nv_bfloat16 g_wkh[D_ * D_],    g_wkl[D_ * D_];
__device__ __align__(16) __nv_bfloat16 g_wvh[D_ * D_],    g_wvl[D_ * D_];
__device__ __align__(16) __nv_bfloat16 g_woh[D_ * D_],    g_wol[D_ * D_];
__device__ __align__(16) __nv_bfloat16 g_w1h[D_ * DH_],   g_w1l[D_ * DH_];
__device__ __align__(16) __nv_bfloat16 g_w2h[DH_ * D_],   g_w2l[DH_ * D_];
__device__ __align__(16) __nv_bfloat16 g_qh [M_ * D_],    g_ql [M_ * D_];
__device__ __align__(16) __nv_bfloat16 g_kh [M_ * D_],    g_kl [M_ * D_];
__device__ __align__(16) __nv_bfloat16 g_vh [M_ * D_],    g_vl [M_ * D_];
__device__ __align__(16) __nv_bfloat16 g_ath[M_ * D_],    g_atl[M_ * D_];
__device__ __align__(16) __nv_bfloat16 g_aoh[M_ * D_],    g_aol[M_ * D_];
__device__ __align__(16) __nv_bfloat16 g_hhh[(size_t)M_ * DH_], g_hhl[(size_t)M_ * DH_];

__device__ __forceinline__ float elu1(float x) { return x > 0.f ? x + 1.f : __expf(x); }

__device__ __forceinline__ void split2(float a, float b, uint32_t& hi, uint32_t& lo) {
    __nv_bfloat162 h; h.x = __float2bfloat16(a); h.y = __float2bfloat16(b);
    __nv_bfloat162 l;
    l.x = __float2bfloat16(a - __bfloat162float(h.x));
    l.y = __float2bfloat16(b - __bfloat162float(h.y));
    hi = *(uint32_t*)&h; lo = *(uint32_t*)&l;
}

// ================= mma helpers ===================================================
__device__ __forceinline__ void cp16(void* dst, const void* src) {
    uint32_t d = (uint32_t)__cvta_generic_to_shared(dst);
    asm volatile("cp.async.cg.shared.global [%0], [%1], 16;" :: "r"(d), "l"(src));
}

#define LDSM4(f, p) do { \
    uint32_t a_ = (uint32_t)__cvta_generic_to_shared(p); \
    asm volatile("ldmatrix.sync.aligned.m8n8.x4.shared.b16 {%0,%1,%2,%3}, [%4];" \
        : "=r"(f[0]), "=r"(f[1]), "=r"(f[2]), "=r"(f[3]) : "r"(a_)); \
} while (0)

#define LDSM4T(f, p) do { \
    uint32_t a_ = (uint32_t)__cvta_generic_to_shared(p); \
    asm volatile("ldmatrix.sync.aligned.m8n8.x4.trans.shared.b16 {%0,%1,%2,%3}, [%4];" \
        : "=r"(f[0]), "=r"(f[1]), "=r"(f[2]), "=r"(f[3]) : "r"(a_)); \
} while (0)

#define MMA16816(d, a, b0, b1) \
    asm volatile("mma.sync.aligned.m16n8k16.row.col.f32.bf16.bf16.f32 " \
        "{%0,%1,%2,%3}, {%4,%5,%6,%7}, {%8,%9}, {%0,%1,%2,%3};" \
        : "+f"(d[0]), "+f"(d[1]), "+f"(d[2]), "+f"(d[3]) \
        : "r"(a[0]), "r"(a[1]), "r"(a[2]), "r"(a[3]), "r"(b0), "r"(b1))

// ================= bf16x3 tensor-core GEMM (unchanged, verified) =================
#define SA_STRIDE 40
#define SB_STRIDE 136
#define SA_STAGE  (128*SA_STRIDE)
#define SB_STAGE  (32*SB_STRIDE)
#define BGEMM_SMEM ((2*SA_STAGE*2 + 2*SB_STAGE*2) * 2)

__device__ __forceinline__ void bg_load_stage(
    const __nv_bfloat16* __restrict__ Ahg, const __nv_bfloat16* __restrict__ Alg,
    const __nv_bfloat16* __restrict__ Bhg, const __nv_bfloat16* __restrict__ Blg,
    __nv_bfloat16* sAh, __nv_bfloat16* sAl, __nv_bfloat16* sBh, __nv_bfloat16* sBl,
    int tid, size_t m0, size_t n0, int Kk, int Nn, int k0)
{
    int arow = tid >> 2, achunk = (tid & 3) << 3;
    int brow = tid >> 3, bchunk = (tid & 7) << 3;
#pragma unroll
    for (int it = 0; it < 2; it++) {
        int r = arow + it * 64;
        size_t go = (m0 + r) * (size_t)Kk + k0 + achunk;
        cp16(sAh + r * SA_STRIDE + achunk, Ahg + go);
        cp16(sAl + r * SA_STRIDE + achunk, Alg + go);
    }
#pragma unroll
    for (int it = 0; it < 2; it++) {
        int c = bchunk + it * 64;
        size_t go = (size_t)(k0 + brow) * Nn + n0 + c;
        cp16(sBh + brow * SB_STRIDE + c, Bhg + go);
        cp16(sBl + brow * SB_STRIDE + c, Blg + go);
    }
    asm volatile("cp.async.commit_group;");
}

__global__ void __launch_bounds__(256)
bgemm_kernel(const __nv_bfloat16* __restrict__ Ahg, const __nv_bfloat16* __restrict__ Alg,
             const __nv_bfloat16* __restrict__ Bhg, const __nv_bfloat16* __restrict__ Blg,
             int Kk, int Nn,
             const float* __restrict__ bias, int relu, const float* __restrict__ resid,
             float* __restrict__ C,
             __nv_bfloat16* __restrict__ Ch, __nv_bfloat16* __restrict__ Cl)
{
    extern __shared__ __nv_bfloat16 smem[];
    __nv_bfloat16* sAh = smem;
    __nv_bfloat16* sAl = smem + 2*SA_STAGE;
    __nv_bfloat16* sBh = smem + 4*SA_STAGE;
    __nv_bfloat16* sBl = smem + 4*SA_STAGE + 2*SB_STAGE;

    int tid = threadIdx.x;
    int warp = tid >> 5, lane = tid & 31;
    int wm = warp >> 1, wn = warp & 1;
    size_t m0 = (size_t)blockIdx.y * 128;
    size_t n0 = (size_t)blockIdx.x * 128;

    float acc[2][8][4];
#pragma unroll
    for (int i = 0; i < 2; i++)
#pragma unroll
        for (int j = 0; j < 8; j++)
#pragma unroll
            for (int t = 0; t < 4; t++) acc[i][j][t] = 0.f;

    int nk = Kk >> 5;
    bg_load_stage(Ahg, Alg, Bhg, Blg, sAh, sAl, sBh, sBl, tid, m0, n0, Kk, Nn, 0);

    for (int kt = 0; kt < nk; kt++) {
        int cur = kt & 1;
        if (kt + 1 < nk) {
            bg_load_stage(Ahg, Alg, Bhg, Blg,
                          sAh + ((kt+1)&1)*SA_STAGE, sAl + ((kt+1)&1)*SA_STAGE,
                          sBh + ((kt+1)&1)*SB_STAGE, sBl + ((kt+1)&1)*SB_STAGE,
                          tid, m0, n0, Kk, Nn, (kt+1)*32);
            asm volatile("cp.async.wait_group 1;");
        } else {
            asm volatile("cp.async.wait_group 0;");
        }
        __syncthreads();

        __nv_bfloat16* ah = sAh + cur*SA_STAGE;
        __nv_bfloat16* al = sAl + cur*SA_STAGE;
        __nv_bfloat16* bh = sBh + cur*SB_STAGE;
        __nv_bfloat16* bl = sBl + cur*SB_STAGE;

#pragma unroll
        for (int k16 = 0; k16 < 32; k16 += 16) {
            uint32_t afh[2][4], afl[2][4], bfh[4][4], bfl[4][4];
#pragma unroll
            for (int mi = 0; mi < 2; mi++) {
                const __nv_bfloat16* pa = ah + (size_t)(wm*32 + mi*16 + (lane & 15)) * SA_STRIDE
                                             + k16 + (lane >> 4) * 8;
                LDSM4(afh[mi], pa);
                const __nv_bfloat16* pl = al + (size_t)(wm*32 + mi*16 + (lane & 15)) * SA_STRIDE
                                             + k16 + (lane >> 4) * 8;
                LDSM4(afl[mi], pl);
            }
#pragma unroll
            for (int nb = 0; nb < 4; nb++) {
                const __nv_bfloat16* pb = bh + (size_t)(k16 + (lane & 15)) * SB_STRIDE
                                             + wn*64 + nb*16 + (lane >> 4) * 8;
                LDSM4T(bfh[nb], pb);
                const __nv_bfloat16* pq = bl + (size_t)(k16 + (lane & 15)) * SB_STRIDE
                                             + wn*64 + nb*16 + (lane >> 4) * 8;
                LDSM4T(bfl[nb], pq);
            }
#pragma unroll
            for (int mi = 0; mi < 2; mi++)
#pragma unroll
                for (int ni = 0; ni < 8; ni++) {
                    int nb = ni >> 1, sel = (ni & 1) * 2;
                    MMA16816(acc[mi][ni], afh[mi], bfh[nb][sel], bfh[nb][sel+1]);
                    MMA16816(acc[mi][ni], afh[mi], bfl[nb][sel], bfl[nb][sel+1]);
                    MMA16816(acc[mi][ni], afl[mi], bfh[nb][sel], bfh[nb][sel+1]);
                }
        }
        __syncthreads();
    }

#pragma unroll
    for (int mi = 0; mi < 2; mi++)
#pragma unroll
        for (int ni = 0; ni < 8; ni++) {
            int col = wn*64 + ni*8 + (lane & 3) * 2;
#pragma unroll
            for (int hh = 0; hh < 2; hh++) {
                int row = wm*32 + mi*16 + (lane >> 2) + hh*8;
                float v0 = acc[mi][ni][hh*2], v1 = acc[mi][ni][hh*2+1];
                size_t o = (m0 + row) * (size_t)Nn + n0 + col;
                if (bias) { v0 += bias[n0+col]; v1 += bias[n0+col+1]; }
                if (resid) { v0 += resid[o]; v1 += resid[o+1]; }
                if (relu) { v0 = fmaxf(v0, 0.f); v1 = fmaxf(v1, 0.f); }
                if (C) { C[o] = v0; C[o+1] = v1; }
                if (Ch) {
                    uint32_t hp, lp;
                    split2(v0, v1, hp, lp);
                    *(uint32_t*)(Ch + o) = hp;
                    *(uint32_t*)(Cl + o) = lp;
                }
            }
        }
}

// ---------------- fp32 -> bf16 hi/lo split --------------------------------------
__global__ void __launch_bounds__(256)
split_kernel(const float4* __restrict__ in, __nv_bfloat162* __restrict__ hi,
             __nv_bfloat162* __restrict__ lo, int nquads)
{
    int i = blockIdx.x * 256 + threadIdx.x;
    if (i >= nquads) return;
    float4 v = in[i];
    uint32_t h0, l0, h1, l1;
    split2(v.x, v.y, h0, l0);
    split2(v.z, v.w, h1, l1);
    hi[2*i]   = *(__nv_bfloat162*)&h0;
    hi[2*i+1] = *(__nv_bfloat162*)&h1;
    lo[2*i]   = *(__nv_bfloat162*)&l0;
    lo[2*i+1] = *(__nv_bfloat162*)&l1;
}

// ================= flash attention (bf16x3 mma) ==================================
// grid (qt 8, seg 8, bh 32), 128 thr (4 warps). Warp owns 16 q-rows of the
// 64-row q tile. K-tiles of 64 keys.  S: A=Q(hi/lo) LDSM4, B=K(hi/lo) LDSM4
// non-trans (pairing regs (0,2)/(1,3)).  P·V: A=P packed from accums, B=V LDSM4T.
#define AT_STR 136
#define AT_TILE (64*AT_STR)          // bf16 elems per tile array
#define ATTN_SMEM_BYTES (6 * AT_TILE * 2)

__global__ void __launch_bounds__(128)
attn_mma_kernel(const __nv_bfloat16* __restrict__ qh, const __nv_bfloat16* __restrict__ ql,
                const __nv_bfloat16* __restrict__ kh, const __nv_bfloat16* __restrict__ kl,
                const __nv_bfloat16* __restrict__ vh, const __nv_bfloat16* __restrict__ vl,
                float* __restrict__ att)
{
    extern __shared__ __nv_bfloat16 sm[];
    __nv_bfloat16* Qh = sm;
    __nv_bfloat16* Ql = sm + AT_TILE;
    __nv_bfloat16* Kh = sm + 2*AT_TILE;
    __nv_bfloat16* Kl = sm + 3*AT_TILE;
    __nv_bfloat16* Vh = sm + 4*AT_TILE;
    __nv_bfloat16* Vl = sm + 5*AT_TILE;

    int qt = blockIdx.x, seg = blockIdx.y, bh = blockIdx.z;
    int b = bh >> 4, h = bh & 15;
    int tid = threadIdx.x, warp = tid >> 5, lane = tid & 31;
    const float scale = 0.08838834764831845f;
    size_t base = ((size_t)(b*S_ + seg*SEG_) * H_ + h) * DK_;

    // load Q tile (64 x 128)
#pragma unroll
    for (int it = 0; it < 8; it++) {
        int e = it*128 + tid, r = e >> 4, c8 = (e & 15) << 3;
        size_t go = base + (size_t)(qt*64 + r)*2048 + c8;
        *(uint4*)(Qh + r*AT_STR + c8) = *(const uint4*)(qh + go);
        *(uint4*)(Ql + r*AT_STR + c8) = *(const uint4*)(ql + go);
    }

    float o[16][4];
#pragma unroll
    for (int t = 0; t < 16; t++)
#pragma unroll
        for (int j = 0; j < 4; j++) o[t][j] = 0.f;
    float m0 = -1e30f, m1 = -1e30f, l0 = 0.f, l1 = 0.f;
    int r0g = qt*64 + warp*16 + (lane >> 2);
    int r1g = r0g + 8;

    for (int kt = 0; kt <= qt; kt++) {
        __syncthreads();
#pragma unroll
        for (int it = 0; it < 8; it++) {
            int e = it*128 + tid, r = e >> 4, c8 = (e & 15) << 3;
            size_t go = base + (size_t)(kt*64 + r)*2048 + c8;
            *(uint4*)(Kh + r*AT_STR + c8) = *(const uint4*)(kh + go);
            *(uint4*)(Kl + r*AT_STR + c8) = *(const uint4*)(kl + go);
            *(uint4*)(Vh + r*AT_STR + c8) = *(const uint4*)(vh + go);
            *(uint4*)(Vl + r*AT_STR + c8) = *(const uint4*)(vl + go);
        }
        __syncthreads();

        // ---- S = Q K^T (3-pass hi/lo) ----
        float s[8][4];
#pragma unroll
        for (int t = 0; t < 8; t++)
#pragma unroll
            for (int j = 0; j < 4; j++) s[t][j] = 0.f;

#pragma unroll
        for (int kk = 0; kk < 8; kk++) {
            uint32_t qa[4], qb[4];
            LDSM4(qa, Qh + (size_t)(warp*16 + (lane & 15))*AT_STR + kk*16 + (lane >> 4)*8);
            LDSM4(qb, Ql + (size_t)(warp*16 + (lane & 15))*AT_STR + kk*16 + (lane >> 4)*8);
#pragma unroll
            for (int ng = 0; ng < 4; ng++) {
                uint32_t kfh[4], kfl[4];
                LDSM4(kfh, Kh + (size_t)(ng*16 + (lane & 15))*AT_STR + kk*16 + (lane >> 4)*8);
                LDSM4(kfl, Kl + (size_t)(ng*16 + (lane & 15))*AT_STR + kk*16 + (lane >> 4)*8);
                MMA16816(s[2*ng],   qa, kfh[0], kfh[2]);
                MMA16816(s[2*ng],   qa, kfl[0], kfl[2]);
                MMA16816(s[2*ng],   qb, kfh[0], kfh[2]);
                MMA16816(s[2*ng+1], qa, kfh[1], kfh[3]);
                MMA16816(s[2*ng+1], qa, kfl[1], kfl[3]);
                MMA16816(s[2*ng+1], qb, kfh[1], kfh[3]);
            }
        }

        // ---- online softmax ----
        float mx0 = -1e30f, mx1 = -1e30f;
#pragma unroll
        for (int t = 0; t < 8; t++) {
            int colb = kt*64 + t*8 + (lane & 3)*2;
            float a0 = s[t][0]*scale, a1 = s[t][1]*scale;
            float a2 = s[t][2]*scale, a3 = s[t][3]*scale;
            if (kt == qt) {
                if (colb     > r0g) a0 = -1e30f;
                if (colb + 1 > r0g) a1 = -1e30f;
                if (colb     > r1g) a2 = -1e30f;
                if (colb + 1 > r1g) a3 = -1e30f;
            }
            s[t][0] = a0; s[t][1] = a1; s[t][2] = a2; s[t][3] = a3;
            mx0 = fmaxf(mx0, fmaxf(a0, a1));
            mx1 = fmaxf(mx1, fmaxf(a2, a3));
        }
        mx0 = fmaxf(mx0, __shfl_xor_sync(0xffffffffu, mx0, 1));
        mx0 = fmaxf(mx0, __shfl_xor_sync(0xffffffffu, mx0, 2));
        mx1 = fmaxf(mx1, __shfl_xor_sync(0xffffffffu, mx1, 1));
        mx1 = fmaxf(mx1, __shfl_xor_sync(0xffffffffu, mx1, 2));
        float m0n = fmaxf(m0, mx0), m1n = fmaxf(m1, mx1);
        float rc0 = __expf(m0 - m0n), rc1 = __expf(m1 - m1n);
        float sum0 = 0.f, sum1 = 0.f;
#pragma unroll
        for (int t = 0; t < 8; t++) {
            s[t][0] = __expf(s[t][0] - m0n); sum0 += s[t][0];
            s[t][1] = __expf(s[t][1] - m0n); sum0 += s[t][1];
            s[t][2] = __expf(s[t][2] - m1n); sum1 += s[t][2];
            s[t][3] = __expf(s[t][3] - m1n); sum1 += s[t][3];
        }
        sum0 += __shfl_xor_sync(0xffffffffu, sum0, 1);
        sum0 += __shfl_xor_sync(0xffffffffu, sum0, 2);
        sum1 += __shfl_xor_sync(0xffffffffu, sum1, 1);
        sum1 += __shfl_xor_sync(0xffffffffu, sum1, 2);
        l0 = l0*rc0 + sum0;  l1 = l1*rc1 + sum1;
        m0 = m0n;  m1 = m1n;
#pragma unroll
        for (int t = 0; t < 16; t++) {
            o[t][0] *= rc0; o[t][1] *= rc0; o[t][2] *= rc1; o[t][3] *= rc1;
        }

        // ---- O += P V (3-pass hi/lo) ----
#pragma unroll
        for (int kk = 0; kk < 4; kk++) {
            uint32_t ah[4], al[4];
            split2(s[2*kk][0],   s[2*kk][1],   ah[0], al[0]);
            split2(s[2*kk][2],   s[2*kk][3],   ah[1], al[1]);
            split2(s[2*kk+1][0], s[2*kk+1][1], ah[2], al[2]);
            split2(s[2*kk+1][2], s[2*kk+1][3], ah[3], al[3]);
#pragma unroll
            for (int dg = 0; dg < 8; dg++) {
                uint32_t vfh[4], vfl[4];
                LDSM4T(vfh, Vh + (size_t)(kk*16 + (lane & 15))*AT_STR + dg*16 + (lane >> 4)*8);
                LDSM4T(vfl, Vl + (size_t)(kk*16 + (lane & 15))*AT_STR + dg*16 + (lane >> 4)*8);
                MMA16816(o[2*dg],   ah, vfh[0], vfh[1]);
                MMA16816(o[2*dg],   al, vfh[0], vfh[1]);
                MMA16816(o[2*dg],   ah, vfl[0], vfl[1]);
                MMA16816(o[2*dg+1], ah, vfh[2], vfh[3]);
                MMA16816(o[2*dg+1], al, vfh[2], vfh[3]);
                MMA16816(o[2*dg+1], ah, vfl[2], vfl[3]);
            }
        }
    }

    float inv0 = 1.f / l0, inv1 = 1.f / l1;
#pragma unroll
    for (int t = 0; t < 16; t++) {
        size_t ro = base + (size_t)(qt*64 + warp*16 + (lane >> 2))*2048 + t*8 + (lane & 3)*2;
        float2 w0; w0.x = o[t][0]*inv0; w0.y = o[t][1]*inv0;
        float2 w1; w1.x = o[t][2]*inv1; w1.y = o[t][3]*inv1;
        *(float2*)(att + ro)          = w0;
        *(float2*)(att + ro + 8*2048) = w1;
    }
}

// ================= memory update: U = sig(K)^T V (bf16x3 mma) ====================
// grid 256 (bh*8+seg), 256 thr (8 warps), warp tile 32x64 of the 128x128 output.
#define MU_KSTR 72
#define MU_KTILE (128*MU_KSTR)
#define MU_VSTR 136
#define MU_VTILE (64*MU_VSTR)
#define MEMUPD_SMEM ((2*MU_KTILE + 2*MU_VTILE) * 2)

__global__ void __launch_bounds__(256)
memupd_mma_kernel(const __nv_bfloat16* __restrict__ kh, const __nv_bfloat16* __restrict__ kl,
                  const __nv_bfloat16* __restrict__ vh, const __nv_bfloat16* __restrict__ vl,
                  float* __restrict__ U, float* __restrict__ zU)
{
    extern __shared__ __nv_bfloat16 sm[];
    __nv_bfloat16* sKh = sm;                      // [dk 128][s 64] (transposed)
    __nv_bfloat16* sKl = sm + MU_KTILE;
    __nv_bfloat16* sVh = sm + 2*MU_KTILE;         // [s 64][dv 128]
    __nv_bfloat16* sVl = sm + 2*MU_KTILE + MU_VTILE;
    __shared__ float zsm[128];

    int seg = blockIdx.x & 7, bhx = blockIdx.x >> 3;
    int b = bhx >> 4, h = bhx & 15;
    int tid = threadIdx.x, warp = tid >> 5, lane = tid & 31;
    int wm = warp >> 1, wn = warp & 1;
    size_t base = ((size_t)(b*S_ + seg*SEG_) * H_ + h) * DK_;

    if (tid < 128) zsm[tid] = 0.f;

    float acc[2][8][4];
#pragma unroll
    for (int i = 0; i < 2; i++)
#pragma unroll
        for (int j = 0; j < 8; j++)
#pragma unroll
            for (int t = 0; t < 4; t++) acc[i][j][t] = 0.f;

    for (int st = 0; st < 8; st++) {
        int s0 = st * 64;
        // build sig(K)^T tile (apply elu to hi+lo, re-split)
#pragma unroll
        for (int it = 0; it < 16; it++) {
            int e = it*256 + tid, s = e >> 6, c2 = e & 63;
            size_t go = base + (size_t)(s0 + s)*2048 + 2*c2;
            __nv_bfloat162 h2 = *(const __nv_bfloat162*)(kh + go);
            __nv_bfloat162 l2 = *(const __nv_bfloat162*)(kl + go);
            float f0 = elu1(__bfloat162float(h2.x) + __bfloat162float(l2.x));
            float f1 = elu1(__bfloat162float(h2.y) + __bfloat162float(l2.y));
            __nv_bfloat16 h0 = __float2bfloat16(f0), h1 = __float2bfloat16(f1);
            sKh[(2*c2)  *MU_KSTR + s] = h0;
            sKh[(2*c2+1)*MU_KSTR + s] = h1;
            sKl[(2*c2)  *MU_KSTR + s] = __float2bfloat16(f0 - __bfloat162float(h0));
            sKl[(2*c2+1)*MU_KSTR + s] = __float2bfloat16(f1 - __bfloat162float(h1));
        }
        // copy V tile
#pragma unroll
        for (int it = 0; it < 4; it++) {
            int e = it*256 + tid, r = e >> 4, c8 = (e & 15) << 3;
            size_t go = base + (size_t)(s0 + r)*2048 + c8;
            *(uint4*)(sVh + r*MU_VSTR + c8) = *(const uint4*)(vh + go);
            *(uint4*)(sVl + r*MU_VSTR + c8) = *(const uint4*)(vl + go);
        }
        __syncthreads();

        // z accumulation (reconstruct hi+lo)
        if (tid < 128) {
            float zz = 0.f;
#pragma unroll 4
            for (int s = 0; s < 64; s++)
                zz += __bfloat162float(sKh[tid*MU_KSTR + s])
                    + __bfloat162float(sKl[tid*MU_KSTR + s]);
            zsm[tid] += zz;
        }

#pragma unroll
        for (int kk = 0; kk < 4; kk++) {
            uint32_t ah[2][4], al[2][4];
#pragma unroll
            for (int mi = 0; mi < 2; mi++) {
                LDSM4(ah[mi], sKh + (size_t)(wm*32 + mi*16 + (lane & 15))*MU_KSTR + kk*16 + (lane >> 4)*8);
                LDSM4(al[mi], sKl + (size_t)(wm*32 + mi*16 + (lane & 15))*MU_KSTR + kk*16 + (lane >> 4)*8);
            }
#pragma unroll
            for (int ng = 0; ng < 4; ng++) {
                uint32_t bh4[4], bl4[4];
                LDSM4T(bh4, sVh + (size_t)(kk*16 + (lane & 15))*MU_VSTR + wn*64 + ng*16 + (lane >> 4)*8);
                LDSM4T(bl4, sVl + (size_t)(kk*16 + (lane & 15))*MU_VSTR + wn*64 + ng*16 + (lane >> 4)*8);
#pragma unroll
                for (int mi = 0; mi < 2; mi++) {
                    MMA16816(acc[mi][2*ng],   ah[mi], bh4[0], bh4[1]);
                    MMA16816(acc[mi][2*ng],   al[mi], bh4[0], bh4[1]);
                    MMA16816(acc[mi][2*ng],   ah[mi], bl4[0], bl4[1]);
                    MMA16816(acc[mi][2*ng+1], ah[mi], bh4[2], bh4[3]);
                    MMA16816(acc[mi][2*ng+1], al[mi], bh4[2], bh4[3]);
                    MMA16816(acc[mi][2*ng+1], ah[mi], bl4[2], bl4[3]);
                }
            }
        }
        __syncthreads();
    }

    size_t ob = (size_t)blockIdx.x * (DK_*DV_);
#pragma unroll
    for (int mi = 0; mi < 2; mi++)
#pragma unroll
        for (int ni = 0; ni < 8; ni++) {
            int col = wn*64 + ni*8 + (lane & 3)*2;
#pragma unroll
            for (int hh = 0; hh < 2; hh++) {
                int row = wm*32 + mi*16 + (lane >> 2) + hh*8;
                float2 w; w.x = acc[mi][ni][hh*2]; w.y = acc[mi][ni][hh*2+1];
                *(float2*)(U + ob + (size_t)row*128 + col) = w;
            }
        }
    if (tid < 128) zU[(size_t)blockIdx.x*128 + tid] = zsm[tid];
}

// ---------------- exclusive prefix over segments --------------------------------
__global__ void __launch_bounds__(256)
prefix_kernel(const float* __restrict__ U, const float* __restrict__ zU,
              float* __restrict__ Mem, float* __restrict__ Z)
{
    int bh = blockIdx.x, tid = threadIdx.x;
    for (int idx = tid; idx < DK_*DV_; idx += 256) {
        float run = 0.f;
#pragma unroll
        for (int sg = 0; sg < NSEG_; sg++) {
            size_t o = ((size_t)(bh*NSEG_ + sg)) * (DK_*DV_) + idx;
            Mem[o] = run;
            run += U[o];
        }
    }
    if (tid < 128) {
        float run = 1.f / 128.f;
#pragma unroll
        for (int sg = 0; sg < NSEG_; sg++) {
            size_t o = (size_t)(bh*NSEG_ + sg) * 128 + tid;
            Z[o] = run;
            run += zU[o];
        }
    }
}

// ================= retrieval + gate combine (bf16x3 mma) =========================
// grid 256 (bh*8+seg), 256 thr (8 warps). mem loaded/split once; sigma(Q) chunks
// of 128 rows; warp owns 16 rows. Writes final att as bf16 hi/lo.
#define RT_STR 136
#define RT_TILE (128*RT_STR)
#define RETR_SMEM (4 * RT_TILE * 2)

__global__ void __launch_bounds__(256)
retrieve_mma_kernel(const __nv_bfloat16* __restrict__ qh, const __nv_bfloat16* __restrict__ ql,
                    const float* __restrict__ Mem, const float* __restrict__ Z,
                    const float* __restrict__ betas, const float* __restrict__ attdot,
                    __nv_bfloat16* __restrict__ ath, __nv_bfloat16* __restrict__ atl)
{
    extern __shared__ __nv_bfloat16 sm[];
    __nv_bfloat16* Mh = sm;                // [dk 128][dv 128]
    __nv_bfloat16* Ml = sm + RT_TILE;
    __nv_bfloat16* Sh = sm + 2*RT_TILE;    // sigma(Q) [s 128][dk 128]
    __nv_bfloat16* Sl = sm + 3*RT_TILE;
    __shared__ float den[128], zz[128], gate[128];

    int seg = blockIdx.x & 7, bhx = blockIdx.x >> 3;
    int b = bhx >> 4, h = bhx & 15;
    int tid = threadIdx.x, warp = tid >> 5, lane = tid & 31;
    size_t base = ((size_t)(b*S_ + seg*SEG_) * H_ + h) * DK_;
    size_t mb = (size_t)blockIdx.x * 16384;

    if (tid < 128) {
        gate[tid] = 1.f / (1.f + __expf(-betas[h*128 + tid]));
        zz[tid]   = Z[(size_t)blockIdx.x*128 + tid];
    }
    // split mem into smem hi/lo
#pragma unroll
    for (int it = 0; it < 16; it++) {
        int e = it*256 + tid, r = e >> 5, c4 = (e & 31) << 2;
        float4 v = *(const float4*)(Mem + mb + (size_t)r*128 + c4);
        uint32_t h0, l0, h1, l1;
        split2(v.x, v.y, h0, l0);
        split2(v.z, v.w, h1, l1);
        *(uint32_t*)(Mh + r*RT_STR + c4)     = h0;
        *(uint32_t*)(Mh + r*RT_STR + c4 + 2) = h1;
        *(uint32_t*)(Ml + r*RT_STR + c4)     = l0;
        *(uint32_t*)(Ml + r*RT_STR + c4 + 2) = l1;
    }
    __syncthreads();

    for (int ch = 0; ch < 4; ch++) {
        int s0 = ch * 128;
        // build sigma(Q) chunk
#pragma unroll
        for (int it = 0; it < 32; it++) {
            int e = it*256 + tid, s = e >> 6, c2 = e & 63;
            size_t go = base + (size_t)(s0 + s)*2048 + 2*c2;
            __nv_bfloat162 h2 = *(const __nv_bfloat162*)(qh + go);
            __nv_bfloat162 l2 = *(const __nv_bfloat162*)(ql + go);
            float f0 = elu1(__bfloat162float(h2.x) + __bfloat162float(l2.x));
            float f1 = elu1(__bfloat162float(h2.y) + __bfloat162float(l2.y));
            uint32_t hp, lp;
            split2(f0, f1, hp, lp);
            *(uint32_t*)(Sh + s*RT_STR + 2*c2) = hp;
            *(uint32_t*)(Sl + s*RT_STR + 2*c2) = lp;
        }
        __syncthreads();
        if (tid < 128) {
            float d = 0.f;
#pragma unroll 4
            for (int dk = 0; dk < 128; dk++)
                d += (__bfloat162float(Sh[tid*RT_STR + dk])
                    + __bfloat162float(Sl[tid*RT_STR + dk])) * zz[dk];
            den[tid] = d;
        }
        __syncthreads();

        float o[16][4];
#pragma unroll
        for (int t = 0; t < 16; t++)
#pragma unroll
            for (int j = 0; j < 4; j++) o[t][j] = 0.f;

#pragma unroll
        for (int kk = 0; kk < 8; kk++) {
            uint32_t qa[4], qb[4];
            LDSM4(qa, Sh + (size_t)(warp*16 + (lane & 15))*RT_STR + kk*16 + (lane >> 4)*8);
            LDSM4(qb, Sl + (size_t)(warp*16 + (lane & 15))*RT_STR + kk*16 + (lane >> 4)*8);
#pragma unroll
            for (int ng = 0; ng < 8; ng++) {
                uint32_t mh4[4], ml4[4];
                LDSM4T(mh4, Mh + (size_t)(kk*16 + (lane & 15))*RT_STR + ng*16 + (lane >> 4)*8);
                LDSM4T(ml4, Ml + (size_t)(kk*16 + (lane & 15))*RT_STR + ng*16 + (lane >> 4)*8);
                MMA16816(o[2*ng],   qa, mh4[0], mh4[1]);
                MMA16816(o[2*ng],   qb, mh4[0], mh4[1]);
                MMA16816(o[2*ng],   qa, ml4[0], ml4[1]);
                MMA16816(o[2*ng+1], qa, mh4[2], mh4[3]);
                MMA16816(o[2*ng+1], qb, mh4[2], mh4[3]);
                MMA16816(o[2*ng+1], qa, ml4[2], ml4[3]);
            }
        }

        float inv0 = 1.f / den[warp*16 + (lane >> 2)];
        float inv1 = 1.f / den[warp*16 + (lane >> 2) + 8];
#pragma unroll
        for (int t = 0; t < 16; t++) {
            int col = t*8 + (lane & 3)*2;
            float g0 = gate[col], g1 = gate[col+1];
            size_t ro = base + (size_t)(s0 + warp*16 + (lane >> 2))*2048 + col;
            float2 d0 = *(const float2*)(attdot + ro);
            float2 d1 = *(const float2*)(attdot + ro + 8*2048);
            float v0 = g0*(o[t][0]*inv0) + (1.f - g0)*d0.x;
            float v1 = g1*(o[t][1]*inv0) + (1.f - g1)*d0.y;
            float v2 = g0*(o[t][2]*inv1) + (1.f - g0)*d1.x;
            float v3 = g1*(o[t][3]*inv1) + (1.f - g1)*d1.y;
            uint32_t hp, lp;
            split2(v0, v1, hp, lp);
            *(uint32_t*)(ath + ro) = hp;
            *(uint32_t*)(atl + ro) = lp;
            split2(v2, v3, hp, lp);
            *(uint32_t*)(ath + ro + 8*2048) = hp;
            *(uint32_t*)(atl + ro + 8*2048) = lp;
        }
        __syncthreads();
    }
}

// ---------------- LayerNorm -----------------------------------------------------
__global__ void __launch_bounds__(256)
ln_kernel(const float* __restrict__ y, const float* __restrict__ gg,
          const float* __restrict__ bb, float* __restrict__ out)
{
    size_t row = blockIdx.x;
    const float* p = y + row * D_;
    int tid = threadIdx.x;
    float4 v0 = *(const float4*)(p + tid*8);
    float4 v1 = *(const float4*)(p + tid*8 + 4);
    float s  = v0.x+v0.y+v0.z+v0.w + v1.x+v1.y+v1.z+v1.w;
    float s2 = v0.x*v0.x+v0.y*v0.y+v0.z*v0.z+v0.w*v0.w
             + v1.x*v1.x+v1.y*v1.y+v1.z*v1.z+v1.w*v1.w;
#pragma unroll
    for (int o = 16; o >= 1; o >>= 1) {
        s  += __shfl_xor_sync(0xffffffffu, s, o);
        s2 += __shfl_xor_sync(0xffffffffu, s2, o);
    }
    __shared__ float red[16];
    __shared__ float stat[2];
    int warp = tid >> 5, lane = tid & 31;
    if (lane == 0) { red[warp] = s; red[warp + 8] = s2; }
    __syncthreads();
    if (tid == 0) {
        float S = 0.f, S2 = 0.f;
#pragma unroll
        for (int w = 0; w < 8; w++) { S += red[w]; S2 += red[w + 8]; }
        float mean = S / (float)D_;
        float var  = S2 / (float)D_ - mean*mean;
        stat[0] = mean;
        stat[1] = rsqrtf(var + 1e-5f);
    }
    __syncthreads();
    float mean = stat[0], inv = stat[1];
    float4 g0 = *(const float4*)(gg + tid*8), g1 = *(const float4*)(gg + tid*8 + 4);
    float4 b0 = *(const float4*)(bb + tid*8), b1 = *(const float4*)(bb + tid*8 + 4);
    float4 o0, o1;
    o0.x = (v0.x-mean)*inv*g0.x + b0.x; o0.y = (v0.y-mean)*inv*g0.y + b0.y;
    o0.z = (v0.z-mean)*inv*g0.z + b0.z; o0.w = (v0.w-mean)*inv*g0.w + b0.w;
    o1.x = (v1.x-mean)*inv*g1.x + b1.x; o1.y = (v1.y-mean)*inv*g1.y + b1.y;
    o1.z = (v1.z-mean)*inv*g1.z + b1.z; o1.w = (v1.w-mean)*inv*g1.w + b1.w;
    *(float4*)(out + row*D_ + tid*8)     = o0;
    *(float4*)(out + row*D_ + tid*8 + 4) = o1;
}

// ---------------- launch --------------------------------------------------------
static inline void split_launch(const float* src, __nv_bfloat16* hi, __nv_bfloat16* lo,
                                size_t nelems)
{
    int nq = (int)(nelems / 4);
    split_kernel<<<(nq + 255)/256, 256>>>((const float4*)src,
                                          (__nv_bfloat162*)hi, (__nv_bfloat162*)lo, nq);
}

extern "C" void kernel_launch(void* const* d_in, const int* in_sizes, int n_in,
                              void* d_out, int out_size)
{
    const float* x     = (const float*)d_in[0];
    const float* Wq    = (const float*)d_in[1];
    const float* Wk    = (const float*)d_in[2];
    const float* Wv    = (const float*)d_in[3];
    const float* Wo    = (const float*)d_in[4];
    const float* betas = (const float*)d_in[5];
    const float* W1    = (const float*)d_in[6];
    const float* b1    = (const float*)d_in[7];
    const float* W2    = (const float*)d_in[8];
    const float* b2    = (const float*)d_in[9];
    const float* ln_g  = (const float*)d_in[10];
    const float* ln_b  = (const float*)d_in[11];
    float* out = (float*)d_out;

    float *att_, *y_, *U_, *zU_, *mem_, *z_;
    cudaGetSymbolAddress((void**)&att_, g_att);
    cudaGetSymbolAddress((void**)&y_,   g_y);
    cudaGetSymbolAddress((void**)&U_,   g_U);
    cudaGetSymbolAddress((void**)&zU_,  g_zU);
    cudaGetSymbolAddress((void**)&mem_, g_mem);
    cudaGetSymbolAddress((void**)&z_,   g_z);

    __nv_bfloat16 *xh,*xl,*wqh,*wql,*wkh,*wkl,*wvh,*wvl,*woh,*wol,
                  *w1h,*w1l,*w2h,*w2l,*ath,*atl,*aoh,*aol,*hhh,*hhl,
                  *qh,*ql,*kh,*kl,*vh,*vl;
    cudaGetSymbolAddress((void**)&xh,  g_xh);  cudaGetSymbolAddress((void**)&xl,  g_xl);
    cudaGetSymbolAddress((void**)&wqh, g_wqh); cudaGetSymbolAddress((void**)&wql, g_wql);
    cudaGetSymbolAddress((void**)&wkh, g_wkh); cudaGetSymbolAddress((void**)&wkl, g_wkl);
    cudaGetSymbolAddress((void**)&wvh, g_wvh); cudaGetSymbolAddress((void**)&wvl, g_wvl);
    cudaGetSymbolAddress((void**)&woh, g_woh); cudaGetSymbolAddress((void**)&wol, g_wol);
    cudaGetSymbolAddress((void**)&w1h, g_w1h); cudaGetSymbolAddress((void**)&w1l, g_w1l);
    cudaGetSymbolAddress((void**)&w2h, g_w2h); cudaGetSymbolAddress((void**)&w2l, g_w2l);
    cudaGetSymbolAddress((void**)&ath, g_ath); cudaGetSymbolAddress((void**)&atl, g_atl);
    cudaGetSymbolAddress((void**)&aoh, g_aoh); cudaGetSymbolAddress((void**)&aol, g_aol);
    cudaGetSymbolAddress((void**)&hhh, g_hhh); cudaGetSymbolAddress((void**)&hhl, g_hhl);
    cudaGetSymbolAddress((void**)&qh,  g_qh);  cudaGetSymbolAddress((void**)&ql,  g_ql);
    cudaGetSymbolAddress((void**)&kh,  g_kh);  cudaGetSymbolAddress((void**)&kl,  g_kl);
    cudaGetSymbolAddress((void**)&vh,  g_vh);  cudaGetSymbolAddress((void**)&vl,  g_vl);

    cudaFuncSetAttribute(bgemm_kernel,
        cudaFuncAttributeMaxDynamicSharedMemorySize, BGEMM_SMEM);
    cudaFuncSetAttribute(attn_mma_kernel,
        cudaFuncAttributeMaxDynamicSharedMemorySize, ATTN_SMEM_BYTES);
    cudaFuncSetAttribute(memupd_mma_kernel,
        cudaFuncAttributeMaxDynamicSharedMemorySize, MEMUPD_SMEM);
    cudaFuncSetAttribute(retrieve_mma_kernel,
        cudaFuncAttributeMaxDynamicSharedMemorySize, RETR_SMEM);

    // splits (weights + x)
    split_launch(x,  xh,  xl,  (size_t)M_ * D_);
    split_launch(Wq, wqh, wql, (size_t)D_ * D_);
    split_launch(Wk, wkh, wkl, (size_t)D_ * D_);
    split_launch(Wv, wvh, wvl, (size_t)D_ * D_);
    split_launch(Wo, woh, wol, (size_t)D_ * D_);
    split_launch(W1, w1h, w1l, (size_t)D_ * DH_);
    split_launch(W2, w2h, w2l, (size_t)DH_ * D_);

    dim3 gProj(D_/128, M_/128);          // (16, 64)
    dim3 gMlp1(DH_/128, M_/128);         // (64, 64)

    // QKV projections -> bf16 hi/lo directly
    bgemm_kernel<<<gProj, 256, BGEMM_SMEM>>>(xh, xl, wqh, wql, D_, D_,
        nullptr, 0, nullptr, nullptr, qh, ql);
    bgemm_kernel<<<gProj, 256, BGEMM_SMEM>>>(xh, xl, wkh, wkl, D_, D_,
        nullptr, 0, nullptr, nullptr, kh, kl);
    bgemm_kernel<<<gProj, 256, BGEMM_SMEM>>>(xh, xl, wvh, wvl, D_, D_,
        nullptr, 0, nullptr, nullptr, vh, vl);

    // attention paths (tensor cores)
    attn_mma_kernel<<<dim3(8, 8, 32), 128, ATTN_SMEM_BYTES>>>(qh, ql, kh, kl, vh, vl, att_);
    memupd_mma_kernel<<<256, 256, MEMUPD_SMEM>>>(kh, kl, vh, vl, U_, zU_);
    prefix_kernel<<<32, 256>>>(U_, zU_, mem_, z_);
    retrieve_mma_kernel<<<256, 256, RETR_SMEM>>>(qh, ql, mem_, z_, betas, att_, ath, atl);

    // Wo / MLP chain on tensor cores
    bgemm_kernel<<<gProj, 256, BGEMM_SMEM>>>(ath, atl, woh, wol, D_, D_,
        nullptr, 0, nullptr, nullptr, aoh, aol);
    bgemm_kernel<<<gMlp1, 256, BGEMM_SMEM>>>(aoh, aol, w1h, w1l, D_, DH_,
        b1, 1, nullptr, nullptr, hhh, hhl);
    bgemm_kernel<<<gProj, 256, BGEMM_SMEM>>>(hhh, hhl, w2h, w2l, DH_, D_,
        b2, 0, x, y_, nullptr, nullptr);
    ln_kernel<<<M_, 256>>>(y_, ln_g, ln_b, out);
}